// round 2
// baseline (speedup 1.0000x reference)
#include <cuda_runtime.h>
#include <math.h>

#define NTOK   4096
#define BATCH  2
#define DIM64  64
#define INNERD 256
#define ROWS   (BATCH * NTOK)   // 8192

// -------------------- device scratch (no allocations allowed) --------------------
__device__ float g_xn  [ROWS * DIM64];          // 2 MB
__device__ float g_x   [ROWS * DIM64];          // 2 MB
__device__ float g_qkv [ROWS * INNERD * 3];     // 25 MB (also reused as MLP hidden)
__device__ float g_dots[(size_t)NTOK * NTOK];   // 67 MB
__device__ float g_attn[(size_t)NTOK * NTOK];   // 67 MB
__device__ float g_av  [ROWS * INNERD];         // 8 MB

// -------------------- LayerNorm over last dim = 64, one warp per row --------------------
__global__ void ln_k(const float* __restrict__ x, const float* __restrict__ g,
                     const float* __restrict__ b, float* __restrict__ y, int rows)
{
    int w    = blockIdx.x * 8 + (threadIdx.x >> 5);
    int lane = threadIdx.x & 31;
    if (w >= rows) return;
    const float* xr = x + (size_t)w * 64;
    float v0 = xr[lane], v1 = xr[lane + 32];
    float s = v0 + v1;
    #pragma unroll
    for (int o = 16; o > 0; o >>= 1) s += __shfl_xor_sync(0xffffffffu, s, o);
    float m  = s * (1.0f / 64.0f);
    float d0 = v0 - m, d1 = v1 - m;
    float q  = d0 * d0 + d1 * d1;
    #pragma unroll
    for (int o = 16; o > 0; o >>= 1) q += __shfl_xor_sync(0xffffffffu, q, o);
    float inv = rsqrtf(q * (1.0f / 64.0f) + 1e-5f);
    float* yr = y + (size_t)w * 64;
    yr[lane]      = d0 * inv * g[lane]      + b[lane];
    yr[lane + 32] = d1 * inv * g[lane + 32] + b[lane + 32];
}

// -------------------- tiled fp32 GEMM: C = alpha*A*B(^T) [+bias][gelu][+resid] ----------
// 64x64 block tile, K-step 16, 256 threads, 4x4 register micro-tile.
// All M,N are multiples of 64 and K multiples of 16 in this problem -> no bounds checks.
template<bool TB>
__global__ void __launch_bounds__(256)
gemm_k(const float* __restrict__ A, int lda,
       const float* __restrict__ B, int ldb,
       float* __restrict__ C, int ldc,
       int K, float alpha,
       const float* __restrict__ bias,
       const float* __restrict__ resid,
       int do_gelu)
{
    __shared__ float As[16][68];
    __shared__ float Bs[16][68];
    int tx = threadIdx.x, ty = threadIdx.y;
    int t  = ty * 16 + tx;
    int m0 = blockIdx.y * 64, n0 = blockIdx.x * 64;

    float acc[4][4] = {};

    int ar  = t / 4;            // row within 64-row tile (A, and B when transposed)
    int ac4 = (t % 4) * 4;      // 4 consecutive k
    int br  = t / 16;           // k row for NN B-tile
    int bc4 = (t % 16) * 4;     // 4 consecutive n

    for (int k0 = 0; k0 < K; k0 += 16) {
        const float* Ap = A + (size_t)(m0 + ar) * lda + k0 + ac4;
        #pragma unroll
        for (int q = 0; q < 4; q++) As[ac4 + q][ar] = Ap[q];
        if (TB) {
            const float* Bp = B + (size_t)(n0 + ar) * ldb + k0 + ac4;
            #pragma unroll
            for (int q = 0; q < 4; q++) Bs[ac4 + q][ar] = Bp[q];
        } else {
            const float* Bp = B + (size_t)(k0 + br) * ldb + n0 + bc4;
            #pragma unroll
            for (int q = 0; q < 4; q++) Bs[br][bc4 + q] = Bp[q];
        }
        __syncthreads();
        #pragma unroll
        for (int kk = 0; kk < 16; kk++) {
            float a[4], b[4];
            #pragma unroll
            for (int i = 0; i < 4; i++) a[i] = As[kk][ty * 4 + i];
            #pragma unroll
            for (int j = 0; j < 4; j++) b[j] = Bs[kk][tx * 4 + j];
            #pragma unroll
            for (int i = 0; i < 4; i++)
                #pragma unroll
                for (int j = 0; j < 4; j++)
                    acc[i][j] = fmaf(a[i], b[j], acc[i][j]);
        }
        __syncthreads();
    }

    #pragma unroll
    for (int i = 0; i < 4; i++) {
        int row = m0 + ty * 4 + i;
        #pragma unroll
        for (int j = 0; j < 4; j++) {
            int col = n0 + tx * 4 + j;
            float v = acc[i][j] * alpha;
            if (bias)    v += bias[col];
            if (do_gelu) v = 0.5f * v * (1.0f + erff(v * 0.70710678118654752f));
            if (resid)   v += resid[(size_t)row * ldc + col];
            C[(size_t)row * ldc + col] = v;
        }
    }
}

// -------------------- attention softmax: mask by A>0, diag=1.0, row softmax ------------
__global__ void attn_softmax_k(const float* __restrict__ dots, const float* __restrict__ Am,
                               float* __restrict__ attn, float* __restrict__ attn_out)
{
    __shared__ float vals[NTOK];
    __shared__ float red[256];
    int row = blockIdx.x, tid = threadIdx.x;
    const float* dr = dots + (size_t)row * NTOK;
    const float* ar = Am   + (size_t)row * NTOK;

    float mx = -3.4e38f;
    for (int j = tid; j < NTOK; j += 256) {
        float v = (ar[j] > 0.0f) ? dr[j] : -9e15f;
        if (j == row) v = 1.0f;
        vals[j] = v;
        mx = fmaxf(mx, v);
    }
    red[tid] = mx; __syncthreads();
    #pragma unroll
    for (int s = 128; s > 0; s >>= 1) { if (tid < s) red[tid] = fmaxf(red[tid], red[tid + s]); __syncthreads(); }
    mx = red[0]; __syncthreads();

    float sum = 0.0f;
    for (int j = tid; j < NTOK; j += 256) { float e = expf(vals[j] - mx); vals[j] = e; sum += e; }
    red[tid] = sum; __syncthreads();
    #pragma unroll
    for (int s = 128; s > 0; s >>= 1) { if (tid < s) red[tid] += red[tid + s]; __syncthreads(); }
    float inv = 1.0f / red[0];

    float* o1 = attn + (size_t)row * NTOK;
    float* o2 = attn_out ? attn_out + (size_t)row * NTOK : nullptr;
    for (int j = tid; j < NTOK; j += 256) {
        float v = vals[j] * inv;
        o1[j] = v;
        if (o2) o2[j] = v;
    }
}

// -------------------- plain row softmax (for dots_softmax output) -----------------------
__global__ void row_softmax_k(const float* __restrict__ dots, float* __restrict__ out)
{
    __shared__ float vals[NTOK];
    __shared__ float red[256];
    int row = blockIdx.x, tid = threadIdx.x;
    const float* dr = dots + (size_t)row * NTOK;

    float mx = -3.4e38f;
    for (int j = tid; j < NTOK; j += 256) { float v = dr[j]; vals[j] = v; mx = fmaxf(mx, v); }
    red[tid] = mx; __syncthreads();
    #pragma unroll
    for (int s = 128; s > 0; s >>= 1) { if (tid < s) red[tid] = fmaxf(red[tid], red[tid + s]); __syncthreads(); }
    mx = red[0]; __syncthreads();

    float sum = 0.0f;
    for (int j = tid; j < NTOK; j += 256) { float e = expf(vals[j] - mx); vals[j] = e; sum += e; }
    red[tid] = sum; __syncthreads();
    #pragma unroll
    for (int s = 128; s > 0; s >>= 1) { if (tid < s) red[tid] += red[tid + s]; __syncthreads(); }
    float inv = 1.0f / red[0];

    float* orow = out + (size_t)row * NTOK;
    for (int j = tid; j < NTOK; j += 256) orow[j] = vals[j] * inv;
}

// -------------------- host orchestration --------------------
extern "C" void kernel_launch(void* const* d_in, const int* in_sizes, int n_in,
                              void* d_out, int out_size)
{
    const float* embed = (const float*)d_in[0];
    const float* Am    = (const float*)d_in[1];
    const float* g1    = (const float*)d_in[2];
    const float* b1    = (const float*)d_in[3];
    const float* Wqkv  = (const float*)d_in[4];
    const float* Wout  = (const float*)d_in[5];
    const float* bout  = (const float*)d_in[6];
    const float* g2    = (const float*)d_in[7];
    const float* b2    = (const float*)d_in[8];
    const float* W1    = (const float*)d_in[9];
    const float* bb1   = (const float*)d_in[10];
    const float* W2    = (const float*)d_in[11];
    const float* bb2   = (const float*)d_in[12];
    const float* gf    = (const float*)d_in[13];
    const float* bf    = (const float*)d_in[14];

    float *xg, *xng, *qkvg, *dotsg, *attng, *avg;
    cudaGetSymbolAddress((void**)&xg,    g_x);
    cudaGetSymbolAddress((void**)&xng,   g_xn);
    cudaGetSymbolAddress((void**)&qkvg,  g_qkv);
    cudaGetSymbolAddress((void**)&dotsg, g_dots);
    cudaGetSymbolAddress((void**)&attng, g_attn);
    cudaGetSymbolAddress((void**)&avg,   g_av);

    float* out_x    = (float*)d_out;                       // [2,4096,64]
    float* out_attn = out_x + (size_t)ROWS * DIM64;        // [4096,4096]
    float* out_ds   = out_attn + (size_t)NTOK * NTOK;      // [4096,4096]

    dim3 blk(16, 16);

    for (int l = 0; l < 2; l++) {
        const float* src = l ? xg : embed;
        // xn = LN(x)
        ln_k<<<ROWS / 8, 256>>>(src, g1 + l * 64, b1 + l * 64, xng, ROWS);
        // qkv = xn @ Wqkv[l]   [8192,64]x[64,768]
        gemm_k<false><<<dim3(768 / 64, ROWS / 64), blk>>>(
            xng, 64, Wqkv + (size_t)l * 64 * 768, 768, qkvg, 768, 64, 1.0f, nullptr, nullptr, 0);
        // dots = 0.125 * q0 @ k0^T   [4096,256]x[4096,256]^T  (batch 0 only!)
        gemm_k<true><<<dim3(64, 64), blk>>>(
            qkvg, 768, qkvg + 256, 768, dotsg, NTOK, 256, 0.125f, nullptr, nullptr, 0);
        // attn = softmax(mask(dots)), diag forced to 1.0; write out_attn on last layer
        attn_softmax_k<<<NTOK, 256>>>(dotsg, Am, attng, (l == 1) ? out_attn : nullptr);
        // dots_softmax output (last layer only)
        if (l == 1) row_softmax_k<<<NTOK, 256>>>(dotsg, out_ds);
        // av[b] = attn @ v[b]   [4096,4096]x[4096,256]
        for (int bb = 0; bb < BATCH; bb++)
            gemm_k<false><<<dim3(INNERD / 64, NTOK / 64), blk>>>(
                attng, NTOK, qkvg + (size_t)bb * NTOK * 768 + 512, 768,
                avg + (size_t)bb * NTOK * INNERD, INNERD, NTOK, 1.0f, nullptr, nullptr, 0);
        // x = xn + (av @ Wout[l] + bout[l])   [8192,256]x[256,64]
        gemm_k<false><<<dim3(1, ROWS / 64), blk>>>(
            avg, INNERD, Wout + (size_t)l * INNERD * 64, 64, xg, 64, INNERD, 1.0f,
            bout + l * 64, xng, 0);
        // xm = LN(x)
        ln_k<<<ROWS / 8, 256>>>(xg, g2 + l * 64, b2 + l * 64, xng, ROWS);
        // h = gelu(xm @ W1 + bb1)  (reuse qkv scratch as hidden)
        gemm_k<false><<<dim3(1, ROWS / 64), blk>>>(
            xng, 64, W1 + (size_t)l * 64 * 64, 64, qkvg, 64, 64, 1.0f,
            bb1 + l * 64, nullptr, 1);
        // x = xm + (h @ W2 + bb2)
        gemm_k<false><<<dim3(1, ROWS / 64), blk>>>(
            qkvg, 64, W2 + (size_t)l * 64 * 64, 64, xg, 64, 64, 1.0f,
            bb2 + l * 64, xng, 0);
    }
    // final LN -> output
    ln_k<<<ROWS / 8, 256>>>(xg, gf, bf, out_x, ROWS);
}

// round 3
// speedup vs baseline: 1.8134x; 1.8134x over previous
#include <cuda_runtime.h>
#include <math.h>

#define NTOK   4096
#define BATCH  2
#define DIM64  64
#define INNERD 256
#define ROWS   (BATCH * NTOK)   // 8192

// -------------------- device scratch (no allocations allowed) --------------------
__device__ float g_xn  [ROWS * DIM64];          // 2 MB
__device__ float g_x   [ROWS * DIM64];          // 2 MB
__device__ float g_qkv [ROWS * INNERD * 3];     // 25 MB (also reused as MLP hidden)
__device__ float g_dots[(size_t)NTOK * NTOK];   // 67 MB
__device__ float g_attn[(size_t)NTOK * NTOK];   // 67 MB
__device__ float g_av  [ROWS * INNERD];         // 8 MB

// -------------------- LayerNorm over last dim = 64, one warp per row --------------------
__global__ void ln_k(const float* __restrict__ x, const float* __restrict__ g,
                     const float* __restrict__ b, float* __restrict__ y, int rows)
{
    int w    = blockIdx.x * 8 + (threadIdx.x >> 5);
    int lane = threadIdx.x & 31;
    if (w >= rows) return;
    const float* xr = x + (size_t)w * 64;
    float v0 = xr[lane], v1 = xr[lane + 32];
    float s = v0 + v1;
    #pragma unroll
    for (int o = 16; o > 0; o >>= 1) s += __shfl_xor_sync(0xffffffffu, s, o);
    float m  = s * (1.0f / 64.0f);
    float d0 = v0 - m, d1 = v1 - m;
    float q  = d0 * d0 + d1 * d1;
    #pragma unroll
    for (int o = 16; o > 0; o >>= 1) q += __shfl_xor_sync(0xffffffffu, q, o);
    float inv = rsqrtf(q * (1.0f / 64.0f) + 1e-5f);
    float* yr = y + (size_t)w * 64;
    yr[lane]      = d0 * inv * g[lane]      + b[lane];
    yr[lane + 32] = d1 * inv * g[lane + 32] + b[lane + 32];
}

// ==================== BIG GEMM: 128x128 tile, 8x8 microtile, double-buffered ============
// C[z] = alpha * A * B[z](^T)      (z batches B and C; A shared when strideAz==0)
// M,N multiples of 128; K multiple of 16. 256 threads.
template<bool TB>
__global__ void __launch_bounds__(256)
gemm128_k(const float* __restrict__ A, int lda, size_t strideAz,
          const float* __restrict__ B, int ldb, size_t strideBz,
          float* __restrict__ C, int ldc, size_t strideCz,
          int K, float alpha)
{
    __shared__ float As[2][16][132];
    __shared__ float Bs[2][16][132];

    const int tid = threadIdx.x;
    const int tx  = tid & 15, ty = tid >> 4;
    const int m0  = blockIdx.y * 128, n0 = blockIdx.x * 128;

    A += (size_t)blockIdx.z * strideAz;
    B += (size_t)blockIdx.z * strideBz;
    C += (size_t)blockIdx.z * strideCz;

    // A loader mapping: chunk c in {tid, tid+256}; row=c>>2 (0..127), kc=(c&3)*4
    const int arow = tid >> 2;
    const int akc  = (tid & 3) << 2;
    const float* Ap0 = A + (size_t)(m0 + arow) * lda + akc;
    const float* Ap1 = Ap0 + (size_t)64 * lda;

    // B loader
    const float* Bp0; const float* Bp1;
    int bkr = 0, bnc = 0;
    if (TB) {   // B is [N,K] row-major: same pattern as A
        Bp0 = B + (size_t)(n0 + arow) * ldb + akc;
        Bp1 = Bp0 + (size_t)64 * ldb;
    } else {    // B is [K,N]: float4 along N. chunk c: krow=c>>5 (0..7), nc=(c&31)*4
        bkr = tid >> 5;
        bnc = (tid & 31) << 2;
        Bp0 = B + (size_t)bkr * ldb + n0 + bnc;
        Bp1 = Bp0 + (size_t)8 * ldb;
    }

    float acc[8][8];
    #pragma unroll
    for (int i = 0; i < 8; i++)
        #pragma unroll
        for (int j = 0; j < 8; j++) acc[i][j] = 0.0f;

    float4 pa0, pa1, pb0, pb1;
    const int KT = K >> 4;

    // ---- load tile 0 ----
    pa0 = *(const float4*)(Ap0);
    pa1 = *(const float4*)(Ap1);
    if (TB) { pb0 = *(const float4*)(Bp0); pb1 = *(const float4*)(Bp1); }
    else    { pb0 = *(const float4*)(Bp0); pb1 = *(const float4*)(Bp1); }

    // ---- store tile 0 ----
    {
        As[0][akc+0][arow] = pa0.x; As[0][akc+1][arow] = pa0.y;
        As[0][akc+2][arow] = pa0.z; As[0][akc+3][arow] = pa0.w;
        As[0][akc+0][arow+64] = pa1.x; As[0][akc+1][arow+64] = pa1.y;
        As[0][akc+2][arow+64] = pa1.z; As[0][akc+3][arow+64] = pa1.w;
        if (TB) {
            Bs[0][akc+0][arow] = pb0.x; Bs[0][akc+1][arow] = pb0.y;
            Bs[0][akc+2][arow] = pb0.z; Bs[0][akc+3][arow] = pb0.w;
            Bs[0][akc+0][arow+64] = pb1.x; Bs[0][akc+1][arow+64] = pb1.y;
            Bs[0][akc+2][arow+64] = pb1.z; Bs[0][akc+3][arow+64] = pb1.w;
        } else {
            *(float4*)&Bs[0][bkr][bnc]     = pb0;
            *(float4*)&Bs[0][bkr + 8][bnc] = pb1;
        }
    }
    __syncthreads();

    const int ty4 = ty << 2, tx4 = tx << 2;

    for (int kt = 0; kt < KT; kt++) {
        const int p = kt & 1;
        if (kt + 1 < KT) {
            const size_t off = (size_t)(kt + 1) * 16;
            pa0 = *(const float4*)(Ap0 + off);
            pa1 = *(const float4*)(Ap1 + off);
            if (TB) {
                pb0 = *(const float4*)(Bp0 + off);
                pb1 = *(const float4*)(Bp1 + off);
            } else {
                pb0 = *(const float4*)(Bp0 + off * ldb);
                pb1 = *(const float4*)(Bp1 + off * ldb);
            }
        }

        #pragma unroll
        for (int kk = 0; kk < 16; kk++) {
            float4 a0 = *(const float4*)&As[p][kk][ty4];
            float4 a1 = *(const float4*)&As[p][kk][64 + ty4];
            float4 b0 = *(const float4*)&Bs[p][kk][tx4];
            float4 b1 = *(const float4*)&Bs[p][kk][64 + tx4];
            float av[8] = {a0.x, a0.y, a0.z, a0.w, a1.x, a1.y, a1.z, a1.w};
            float bv[8] = {b0.x, b0.y, b0.z, b0.w, b1.x, b1.y, b1.z, b1.w};
            #pragma unroll
            for (int i = 0; i < 8; i++)
                #pragma unroll
                for (int j = 0; j < 8; j++)
                    acc[i][j] = fmaf(av[i], bv[j], acc[i][j]);
        }

        if (kt + 1 < KT) {
            const int q = p ^ 1;
            As[q][akc+0][arow] = pa0.x; As[q][akc+1][arow] = pa0.y;
            As[q][akc+2][arow] = pa0.z; As[q][akc+3][arow] = pa0.w;
            As[q][akc+0][arow+64] = pa1.x; As[q][akc+1][arow+64] = pa1.y;
            As[q][akc+2][arow+64] = pa1.z; As[q][akc+3][arow+64] = pa1.w;
            if (TB) {
                Bs[q][akc+0][arow] = pb0.x; Bs[q][akc+1][arow] = pb0.y;
                Bs[q][akc+2][arow] = pb0.z; Bs[q][akc+3][arow] = pb0.w;
                Bs[q][akc+0][arow+64] = pb1.x; Bs[q][akc+1][arow+64] = pb1.y;
                Bs[q][akc+2][arow+64] = pb1.z; Bs[q][akc+3][arow+64] = pb1.w;
            } else {
                *(float4*)&Bs[q][bkr][bnc]     = pb0;
                *(float4*)&Bs[q][bkr + 8][bnc] = pb1;
            }
            __syncthreads();
        }
    }

    // ---- epilogue: C = alpha * acc ----
    #pragma unroll
    for (int i = 0; i < 8; i++) {
        const int row = m0 + ((i < 4) ? (ty4 + i) : (64 + ty4 + i - 4));
        float* cr = C + (size_t)row * ldc + n0;
        float4 v0 = make_float4(acc[i][0]*alpha, acc[i][1]*alpha, acc[i][2]*alpha, acc[i][3]*alpha);
        float4 v1 = make_float4(acc[i][4]*alpha, acc[i][5]*alpha, acc[i][6]*alpha, acc[i][7]*alpha);
        *(float4*)(cr + tx4)      = v0;
        *(float4*)(cr + 64 + tx4) = v1;
    }
}

// -------------------- small tiled fp32 GEMM (kept for N=64 projections) -----------------
template<bool TB>
__global__ void __launch_bounds__(256)
gemm_k(const float* __restrict__ A, int lda,
       const float* __restrict__ B, int ldb,
       float* __restrict__ C, int ldc,
       int K, float alpha,
       const float* __restrict__ bias,
       const float* __restrict__ resid,
       int do_gelu)
{
    __shared__ float As[16][68];
    __shared__ float Bs[16][68];
    int tx = threadIdx.x, ty = threadIdx.y;
    int t  = ty * 16 + tx;
    int m0 = blockIdx.y * 64, n0 = blockIdx.x * 64;

    float acc[4][4] = {};

    int ar  = t / 4;
    int ac4 = (t % 4) * 4;
    int br  = t / 16;
    int bc4 = (t % 16) * 4;

    for (int k0 = 0; k0 < K; k0 += 16) {
        const float* Ap = A + (size_t)(m0 + ar) * lda + k0 + ac4;
        #pragma unroll
        for (int q = 0; q < 4; q++) As[ac4 + q][ar] = Ap[q];
        if (TB) {
            const float* Bp = B + (size_t)(n0 + ar) * ldb + k0 + ac4;
            #pragma unroll
            for (int q = 0; q < 4; q++) Bs[ac4 + q][ar] = Bp[q];
        } else {
            const float* Bp = B + (size_t)(k0 + br) * ldb + n0 + bc4;
            #pragma unroll
            for (int q = 0; q < 4; q++) Bs[br][bc4 + q] = Bp[q];
        }
        __syncthreads();
        #pragma unroll
        for (int kk = 0; kk < 16; kk++) {
            float a[4], b[4];
            #pragma unroll
            for (int i = 0; i < 4; i++) a[i] = As[kk][ty * 4 + i];
            #pragma unroll
            for (int j = 0; j < 4; j++) b[j] = Bs[kk][tx * 4 + j];
            #pragma unroll
            for (int i = 0; i < 4; i++)
                #pragma unroll
                for (int j = 0; j < 4; j++)
                    acc[i][j] = fmaf(a[i], b[j], acc[i][j]);
        }
        __syncthreads();
    }

    #pragma unroll
    for (int i = 0; i < 4; i++) {
        int row = m0 + ty * 4 + i;
        #pragma unroll
        for (int j = 0; j < 4; j++) {
            int col = n0 + tx * 4 + j;
            float v = acc[i][j] * alpha;
            if (bias)    v += bias[col];
            if (do_gelu) v = 0.5f * v * (1.0f + erff(v * 0.70710678118654752f));
            if (resid)   v += resid[(size_t)row * ldc + col];
            C[(size_t)row * ldc + col] = v;
        }
    }
}

// -------------------- attention softmax: mask by A>0, diag=1.0, row softmax ------------
__global__ void attn_softmax_k(const float* __restrict__ dots, const float* __restrict__ Am,
                               float* __restrict__ attn)
{
    __shared__ float vals[NTOK];
    __shared__ float red[256];
    int row = blockIdx.x, tid = threadIdx.x;
    const float* dr = dots + (size_t)row * NTOK;
    const float* ar = Am   + (size_t)row * NTOK;

    float mx = -3.4e38f;
    for (int j = tid; j < NTOK; j += 256) {
        float v = (ar[j] > 0.0f) ? dr[j] : -9e15f;
        if (j == row) v = 1.0f;
        vals[j] = v;
        mx = fmaxf(mx, v);
    }
    red[tid] = mx; __syncthreads();
    #pragma unroll
    for (int s = 128; s > 0; s >>= 1) { if (tid < s) red[tid] = fmaxf(red[tid], red[tid + s]); __syncthreads(); }
    mx = red[0]; __syncthreads();

    float sum = 0.0f;
    for (int j = tid; j < NTOK; j += 256) { float e = expf(vals[j] - mx); vals[j] = e; sum += e; }
    red[tid] = sum; __syncthreads();
    #pragma unroll
    for (int s = 128; s > 0; s >>= 1) { if (tid < s) red[tid] += red[tid + s]; __syncthreads(); }
    float inv = 1.0f / red[0];

    float* o1 = attn + (size_t)row * NTOK;
    for (int j = tid; j < NTOK; j += 256) o1[j] = vals[j] * inv;
}

// ----- last layer: masked softmax (-> attn scratch + attn output) AND plain softmax -----
__global__ void dual_softmax_k(const float* __restrict__ dots, const float* __restrict__ Am,
                               float* __restrict__ attn, float* __restrict__ attn_out,
                               float* __restrict__ ds_out)
{
    __shared__ float rawv[NTOK];
    __shared__ float mskv[NTOK];
    __shared__ float red[256];
    int row = blockIdx.x, tid = threadIdx.x;
    const float* dr = dots + (size_t)row * NTOK;
    const float* ar = Am   + (size_t)row * NTOK;

    float mxr = -3.4e38f, mxm = -3.4e38f;
    for (int j = tid; j < NTOK; j += 256) {
        float d = dr[j];
        float v = (ar[j] > 0.0f) ? d : -9e15f;
        if (j == row) v = 1.0f;
        rawv[j] = d; mskv[j] = v;
        mxr = fmaxf(mxr, d); mxm = fmaxf(mxm, v);
    }
    // masked max
    red[tid] = mxm; __syncthreads();
    #pragma unroll
    for (int s = 128; s > 0; s >>= 1) { if (tid < s) red[tid] = fmaxf(red[tid], red[tid + s]); __syncthreads(); }
    mxm = red[0]; __syncthreads();
    // raw max
    red[tid] = mxr; __syncthreads();
    #pragma unroll
    for (int s = 128; s > 0; s >>= 1) { if (tid < s) red[tid] = fmaxf(red[tid], red[tid + s]); __syncthreads(); }
    mxr = red[0]; __syncthreads();

    float sm = 0.0f, sr = 0.0f;
    for (int j = tid; j < NTOK; j += 256) {
        float em = expf(mskv[j] - mxm); mskv[j] = em; sm += em;
        float er = expf(rawv[j] - mxr); rawv[j] = er; sr += er;
    }
    red[tid] = sm; __syncthreads();
    #pragma unroll
    for (int s = 128; s > 0; s >>= 1) { if (tid < s) red[tid] += red[tid + s]; __syncthreads(); }
    sm = red[0]; __syncthreads();
    red[tid] = sr; __syncthreads();
    #pragma unroll
    for (int s = 128; s > 0; s >>= 1) { if (tid < s) red[tid] += red[tid + s]; __syncthreads(); }
    sr = red[0];

    float invm = 1.0f / sm, invr = 1.0f / sr;
    float* o1 = attn     + (size_t)row * NTOK;
    float* o2 = attn_out + (size_t)row * NTOK;
    float* o3 = ds_out   + (size_t)row * NTOK;
    for (int j = tid; j < NTOK; j += 256) {
        float v = mskv[j] * invm;
        o1[j] = v; o2[j] = v;
        o3[j] = rawv[j] * invr;
    }
}

// -------------------- host orchestration --------------------
extern "C" void kernel_launch(void* const* d_in, const int* in_sizes, int n_in,
                              void* d_out, int out_size)
{
    const float* embed = (const float*)d_in[0];
    const float* Am    = (const float*)d_in[1];
    const float* g1    = (const float*)d_in[2];
    const float* b1    = (const float*)d_in[3];
    const float* Wqkv  = (const float*)d_in[4];
    const float* Wout  = (const float*)d_in[5];
    const float* bout  = (const float*)d_in[6];
    const float* g2    = (const float*)d_in[7];
    const float* b2    = (const float*)d_in[8];
    const float* W1    = (const float*)d_in[9];
    const float* bb1   = (const float*)d_in[10];
    const float* W2    = (const float*)d_in[11];
    const float* bb2   = (const float*)d_in[12];
    const float* gf    = (const float*)d_in[13];
    const float* bf    = (const float*)d_in[14];

    float *xg, *xng, *qkvg, *dotsg, *attng, *avg;
    cudaGetSymbolAddress((void**)&xg,    g_x);
    cudaGetSymbolAddress((void**)&xng,   g_xn);
    cudaGetSymbolAddress((void**)&qkvg,  g_qkv);
    cudaGetSymbolAddress((void**)&dotsg, g_dots);
    cudaGetSymbolAddress((void**)&attng, g_attn);
    cudaGetSymbolAddress((void**)&avg,   g_av);

    float* out_x    = (float*)d_out;                       // [2,4096,64]
    float* out_attn = out_x + (size_t)ROWS * DIM64;        // [4096,4096]
    float* out_ds   = out_attn + (size_t)NTOK * NTOK;      // [4096,4096]

    dim3 blk(16, 16);

    for (int l = 0; l < 2; l++) {
        const float* src = l ? xg : embed;
        // xn = LN(x)
        ln_k<<<ROWS / 8, 256>>>(src, g1 + l * 64, b1 + l * 64, xng, ROWS);
        // qkv = xn @ Wqkv[l]   [8192,64]x[64,768]
        gemm128_k<false><<<dim3(768 / 128, ROWS / 128, 1), 256>>>(
            xng, 64, 0, Wqkv + (size_t)l * 64 * 768, 768, 0, qkvg, 768, 0, 64, 1.0f);
        // dots = 0.125 * q0 @ k0^T   [4096,256]x[4096,256]^T  (batch 0 only)
        gemm128_k<true><<<dim3(NTOK / 128, NTOK / 128, 1), 256>>>(
            qkvg, 768, 0, qkvg + 256, 768, 0, dotsg, NTOK, 0, 256, 0.125f);
        // softmax (masked; also dots_softmax output on last layer)
        if (l == 1)
            dual_softmax_k<<<NTOK, 256>>>(dotsg, Am, attng, out_attn, out_ds);
        else
            attn_softmax_k<<<NTOK, 256>>>(dotsg, Am, attng);
        // av[b] = attn @ v[b]   [4096,4096]x[4096,256], batched over z
        gemm128_k<false><<<dim3(INNERD / 128, NTOK / 128, BATCH), 256>>>(
            attng, NTOK, 0,
            qkvg + 512, 768, (size_t)NTOK * 768,
            avg, INNERD, (size_t)NTOK * INNERD,
            NTOK, 1.0f);
        // x = xn + (av @ Wout[l] + bout[l])   [8192,256]x[256,64]
        gemm_k<false><<<dim3(1, ROWS / 64), blk>>>(
            avg, INNERD, Wout + (size_t)l * INNERD * 64, 64, xg, 64, INNERD, 1.0f,
            bout + l * 64, xng, 0);
        // xm = LN(x)
        ln_k<<<ROWS / 8, 256>>>(xg, g2 + l * 64, b2 + l * 64, xng, ROWS);
        // h = gelu(xm @ W1 + bb1)  (reuse qkv scratch as hidden)
        gemm_k<false><<<dim3(1, ROWS / 64), blk>>>(
            xng, 64, W1 + (size_t)l * 64 * 64, 64, qkvg, 64, 64, 1.0f,
            bb1 + l * 64, nullptr, 1);
        // x = xm + (h @ W2 + bb2)
        gemm_k<false><<<dim3(1, ROWS / 64), blk>>>(
            qkvg, 64, W2 + (size_t)l * 64 * 64, 64, xg, 64, 64, 1.0f,
            bb2 + l * 64, xng, 0);
    }
    // final LN -> output
    ln_k<<<ROWS / 8, 256>>>(xg, gf, bf, out_x, ROWS);
}

// round 4
// speedup vs baseline: 3.8491x; 2.1225x over previous
#include <cuda_runtime.h>
#include <math.h>
#include <stdint.h>

#define NTOK   4096
#define BATCH  2
#define DIM64  64
#define INNERD 256
#define ROWS   (BATCH * NTOK)   // 8192

// -------------------- device scratch --------------------
__device__ float g_xn  [ROWS * DIM64];
__device__ float g_x   [ROWS * DIM64];
__device__ float g_qkv [ROWS * INNERD * 3];
__device__ float g_dots[(size_t)NTOK * NTOK];
__device__ float g_attn[(size_t)NTOK * NTOK];
__device__ float g_av  [ROWS * INNERD];
__device__ float g_vT  [BATCH * INNERD * NTOK];   // V transposed: [z][dh][token]
__device__ float g_wT  [768 * 64];                // Wqkv[l] transposed: [768][64]

// -------------------- helpers --------------------
__device__ __forceinline__ float to_tf32(float x) {
    uint32_t r;
    asm("cvt.rna.tf32.f32 %0, %1;" : "=r"(r) : "f"(x));
    return __uint_as_float(r);
}

__device__ __forceinline__ void mma_tf32(float c[4], float a0, float a1, float a2, float a3,
                                         float b0, float b1) {
    asm volatile(
        "mma.sync.aligned.m16n8k8.row.col.f32.tf32.tf32.f32 "
        "{%0,%1,%2,%3}, {%4,%5,%6,%7}, {%8,%9}, {%0,%1,%2,%3};"
        : "+f"(c[0]), "+f"(c[1]), "+f"(c[2]), "+f"(c[3])
        : "r"(__float_as_uint(a0)), "r"(__float_as_uint(a1)),
          "r"(__float_as_uint(a2)), "r"(__float_as_uint(a3)),
          "r"(__float_as_uint(b0)), "r"(__float_as_uint(b1)));
}

// ==================== TF32 tensor-core NT GEMM ====================
// C[z][M,N] = alpha * A[z] (M,K) * B[z] (N,K)^T
// M,N multiples of 128; K multiple of 32. 256 threads, 8 warps (4M x 2N),
// warp tile 32x64 (2 m16-tiles x 8 n8-tiles), k-stage 32, double-buffered.
#define SPITCH 36
#define ASTG   (128 * SPITCH)                 // floats per A stage
#define AS(p, m, k) sm[(p) * ASTG + (m) * SPITCH + (k)]
#define BS(p, n, k) sm[2 * ASTG + (p) * ASTG + (n) * SPITCH + (k)]
#define GEMM_TC_SMEM (4 * ASTG * (int)sizeof(float))   // 73728 bytes

__global__ void gemm_tc_k(const float* __restrict__ A, int lda, size_t sAz,
                          const float* __restrict__ B, int ldb, size_t sBz,
                          float* __restrict__ C, int ldc, size_t sCz,
                          int K, float alpha)
{
    extern __shared__ float sm[];
    const int tid  = threadIdx.x;
    const int wid  = tid >> 5, lane = tid & 31;
    const int wm   = wid & 3,  wn   = wid >> 2;
    const int gid  = lane >> 2, tig = lane & 3;
    const int m0   = blockIdx.y * 128, n0 = blockIdx.x * 128;

    A += (size_t)blockIdx.z * sAz;
    B += (size_t)blockIdx.z * sBz;
    C += (size_t)blockIdx.z * sCz;

    // loader mapping: 4 float4 chunks per thread per operand per stage
    int lrow[4], lkq[4];
    #pragma unroll
    for (int i = 0; i < 4; i++) {
        int c = tid + i * 256;
        lrow[i] = c >> 3;
        lkq[i]  = (c & 7) << 2;
    }

    float acc[2][8][4];
    #pragma unroll
    for (int mt = 0; mt < 2; mt++)
        #pragma unroll
        for (int nt = 0; nt < 8; nt++)
            #pragma unroll
            for (int q = 0; q < 4; q++) acc[mt][nt][q] = 0.0f;

    float4 pa[4], pb[4];
    const int KT = K >> 5;

    // prefetch stage 0
    #pragma unroll
    for (int i = 0; i < 4; i++) {
        pa[i] = *(const float4*)(A + (size_t)(m0 + lrow[i]) * lda + lkq[i]);
        pb[i] = *(const float4*)(B + (size_t)(n0 + lrow[i]) * ldb + lkq[i]);
    }
    #pragma unroll
    for (int i = 0; i < 4; i++) {
        float4 va = make_float4(to_tf32(pa[i].x), to_tf32(pa[i].y), to_tf32(pa[i].z), to_tf32(pa[i].w));
        float4 vb = make_float4(to_tf32(pb[i].x), to_tf32(pb[i].y), to_tf32(pb[i].z), to_tf32(pb[i].w));
        *(float4*)&AS(0, lrow[i], lkq[i]) = va;
        *(float4*)&BS(0, lrow[i], lkq[i]) = vb;
    }
    __syncthreads();

    for (int kt = 0; kt < KT; kt++) {
        const int p = kt & 1;
        if (kt + 1 < KT) {
            const int k0 = (kt + 1) << 5;
            #pragma unroll
            for (int i = 0; i < 4; i++) {
                pa[i] = *(const float4*)(A + (size_t)(m0 + lrow[i]) * lda + k0 + lkq[i]);
                pb[i] = *(const float4*)(B + (size_t)(n0 + lrow[i]) * ldb + k0 + lkq[i]);
            }
        }

        #pragma unroll
        for (int ks = 0; ks < 4; ks++) {
            const int kb = ks << 3;
            float a[2][4];
            #pragma unroll
            for (int mt = 0; mt < 2; mt++) {
                const int mr = wm * 32 + mt * 16 + gid;
                a[mt][0] = AS(p, mr,     kb + tig);
                a[mt][1] = AS(p, mr + 8, kb + tig);
                a[mt][2] = AS(p, mr,     kb + tig + 4);
                a[mt][3] = AS(p, mr + 8, kb + tig + 4);
            }
            #pragma unroll
            for (int nt = 0; nt < 8; nt++) {
                const int nr = wn * 64 + nt * 8 + gid;
                float b0 = BS(p, nr, kb + tig);
                float b1 = BS(p, nr, kb + tig + 4);
                mma_tf32(acc[0][nt], a[0][0], a[0][1], a[0][2], a[0][3], b0, b1);
                mma_tf32(acc[1][nt], a[1][0], a[1][1], a[1][2], a[1][3], b0, b1);
            }
        }

        if (kt + 1 < KT) {
            const int q = p ^ 1;
            #pragma unroll
            for (int i = 0; i < 4; i++) {
                float4 va = make_float4(to_tf32(pa[i].x), to_tf32(pa[i].y), to_tf32(pa[i].z), to_tf32(pa[i].w));
                float4 vb = make_float4(to_tf32(pb[i].x), to_tf32(pb[i].y), to_tf32(pb[i].z), to_tf32(pb[i].w));
                *(float4*)&AS(q, lrow[i], lkq[i]) = va;
                *(float4*)&BS(q, lrow[i], lkq[i]) = vb;
            }
            __syncthreads();
        }
    }

    // epilogue
    #pragma unroll
    for (int mt = 0; mt < 2; mt++) {
        const int row = m0 + wm * 32 + mt * 16 + gid;
        #pragma unroll
        for (int nt = 0; nt < 8; nt++) {
            const int col = n0 + wn * 64 + nt * 8 + tig * 2;
            float2 v0 = make_float2(acc[mt][nt][0] * alpha, acc[mt][nt][1] * alpha);
            float2 v1 = make_float2(acc[mt][nt][2] * alpha, acc[mt][nt][3] * alpha);
            *(float2*)(C + (size_t)row * ldc + col)       = v0;
            *(float2*)(C + (size_t)(row + 8) * ldc + col) = v1;
        }
    }
}

// -------------------- 32x32 transpose: dst[c][r] = src[r][c] --------------------
__global__ void transpose_k(const float* __restrict__ src, int lds,
                            float* __restrict__ dst, int ldd)
{
    __shared__ float t[32][33];
    int c0 = blockIdx.x * 32, r0 = blockIdx.y * 32;
    int tx = threadIdx.x, ty = threadIdx.y;
    #pragma unroll
    for (int j = 0; j < 32; j += 8)
        t[ty + j][tx] = src[(size_t)(r0 + ty + j) * lds + c0 + tx];
    __syncthreads();
    #pragma unroll
    for (int j = 0; j < 32; j += 8)
        dst[(size_t)(c0 + ty + j) * ldd + r0 + tx] = t[tx][ty + j];
}

// -------------------- LayerNorm (dim 64), one warp per row --------------------
__global__ void ln_k(const float* __restrict__ x, const float* __restrict__ g,
                     const float* __restrict__ b, float* __restrict__ y, int rows)
{
    int w    = blockIdx.x * 8 + (threadIdx.x >> 5);
    int lane = threadIdx.x & 31;
    if (w >= rows) return;
    const float* xr = x + (size_t)w * 64;
    float v0 = xr[lane], v1 = xr[lane + 32];
    float s = v0 + v1;
    #pragma unroll
    for (int o = 16; o > 0; o >>= 1) s += __shfl_xor_sync(0xffffffffu, s, o);
    float m  = s * (1.0f / 64.0f);
    float d0 = v0 - m, d1 = v1 - m;
    float q  = d0 * d0 + d1 * d1;
    #pragma unroll
    for (int o = 16; o > 0; o >>= 1) q += __shfl_xor_sync(0xffffffffu, q, o);
    float inv = rsqrtf(q * (1.0f / 64.0f) + 1e-5f);
    float* yr = y + (size_t)w * 64;
    yr[lane]      = d0 * inv * g[lane]      + b[lane];
    yr[lane + 32] = d1 * inv * g[lane + 32] + b[lane + 32];
}

// -------------------- small fp32 GEMM (N=64 projections, fused epilogue) ----------------
__global__ void __launch_bounds__(256)
gemm_k(const float* __restrict__ A, int lda,
       const float* __restrict__ B, int ldb,
       float* __restrict__ C, int ldc,
       int K,
       const float* __restrict__ bias,
       const float* __restrict__ resid,
       int do_gelu)
{
    __shared__ float As[16][68];
    __shared__ float Bs[16][68];
    int tx = threadIdx.x, ty = threadIdx.y;
    int t  = ty * 16 + tx;
    int m0 = blockIdx.y * 64, n0 = blockIdx.x * 64;

    float acc[4][4] = {};
    int ar  = t / 4;
    int ac4 = (t % 4) * 4;
    int br  = t / 16;
    int bc4 = (t % 16) * 4;

    for (int k0 = 0; k0 < K; k0 += 16) {
        const float* Ap = A + (size_t)(m0 + ar) * lda + k0 + ac4;
        #pragma unroll
        for (int q = 0; q < 4; q++) As[ac4 + q][ar] = Ap[q];
        const float* Bp = B + (size_t)(k0 + br) * ldb + n0 + bc4;
        #pragma unroll
        for (int q = 0; q < 4; q++) Bs[br][bc4 + q] = Bp[q];
        __syncthreads();
        #pragma unroll
        for (int kk = 0; kk < 16; kk++) {
            float a[4], b[4];
            #pragma unroll
            for (int i = 0; i < 4; i++) a[i] = As[kk][ty * 4 + i];
            #pragma unroll
            for (int j = 0; j < 4; j++) b[j] = Bs[kk][tx * 4 + j];
            #pragma unroll
            for (int i = 0; i < 4; i++)
                #pragma unroll
                for (int j = 0; j < 4; j++)
                    acc[i][j] = fmaf(a[i], b[j], acc[i][j]);
        }
        __syncthreads();
    }

    #pragma unroll
    for (int i = 0; i < 4; i++) {
        int row = m0 + ty * 4 + i;
        #pragma unroll
        for (int j = 0; j < 4; j++) {
            int col = n0 + tx * 4 + j;
            float v = acc[i][j];
            if (bias)    v += bias[col];
            if (do_gelu) v = 0.5f * v * (1.0f + erff(v * 0.70710678118654752f));
            if (resid)   v += resid[(size_t)row * ldc + col];
            C[(size_t)row * ldc + col] = v;
        }
    }
}

// -------------------- block reduction helpers --------------------
__device__ __forceinline__ float blk_max(float v, float* wred, int wid, int lane) {
    #pragma unroll
    for (int o = 16; o > 0; o >>= 1) v = fmaxf(v, __shfl_xor_sync(0xffffffffu, v, o));
    if (lane == 0) wred[wid] = v;
    __syncthreads();
    float r = wred[0];
    #pragma unroll
    for (int i = 1; i < 8; i++) r = fmaxf(r, wred[i]);
    __syncthreads();
    return r;
}
__device__ __forceinline__ float blk_sum(float v, float* wred, int wid, int lane) {
    #pragma unroll
    for (int o = 16; o > 0; o >>= 1) v += __shfl_xor_sync(0xffffffffu, v, o);
    if (lane == 0) wred[wid] = v;
    __syncthreads();
    float r = 0.0f;
    #pragma unroll
    for (int i = 1; i < 8; i++) r += wred[i];
    r += wred[0];
    __syncthreads();
    return r;
}

// -------------------- masked softmax (A>0 mask, diag=1.0), float4 ------------------
__global__ void attn_softmax_k(const float* __restrict__ dots, const float* __restrict__ Am,
                               float* __restrict__ attn)
{
    __shared__ float4 vals[NTOK / 4];
    __shared__ float wred[8];
    const int row = blockIdx.x, tid = threadIdx.x;
    const int wid = tid >> 5, lane = tid & 31;
    const float4* dr = (const float4*)(dots + (size_t)row * NTOK);
    const float4* ar = (const float4*)(Am   + (size_t)row * NTOK);
    const int dj = row >> 2, dl = row & 3;

    float mx = -3.4e38f;
    #pragma unroll
    for (int j = tid; j < NTOK / 4; j += 256) {
        float4 d = dr[j], a = ar[j], v;
        v.x = (a.x > 0.0f) ? d.x : -9e15f;
        v.y = (a.y > 0.0f) ? d.y : -9e15f;
        v.z = (a.z > 0.0f) ? d.z : -9e15f;
        v.w = (a.w > 0.0f) ? d.w : -9e15f;
        if (j == dj) ((float*)&v)[dl] = 1.0f;
        vals[j] = v;
        mx = fmaxf(fmaxf(fmaxf(mx, v.x), v.y), fmaxf(v.z, v.w));
    }
    mx = blk_max(mx, wred, wid, lane);

    float sum = 0.0f;
    #pragma unroll
    for (int j = tid; j < NTOK / 4; j += 256) {
        float4 v = vals[j];
        v.x = __expf(v.x - mx); v.y = __expf(v.y - mx);
        v.z = __expf(v.z - mx); v.w = __expf(v.w - mx);
        vals[j] = v;
        sum += (v.x + v.y) + (v.z + v.w);
    }
    sum = blk_sum(sum, wred, wid, lane);
    float inv = 1.0f / sum;

    float4* o1 = (float4*)(attn + (size_t)row * NTOK);
    #pragma unroll
    for (int j = tid; j < NTOK / 4; j += 256) {
        float4 v = vals[j];
        o1[j] = make_float4(v.x * inv, v.y * inv, v.z * inv, v.w * inv);
    }
}

// ----- last layer: masked softmax (attn + attn_out) AND plain softmax (ds_out) -----
__global__ void dual_softmax_k(const float* __restrict__ dots, const float* __restrict__ Am,
                               float* __restrict__ attn, float* __restrict__ attn_out,
                               float* __restrict__ ds_out)
{
    __shared__ float4 rawv[NTOK / 4];
    __shared__ float4 mskv[NTOK / 4];
    __shared__ float wred[8];
    const int row = blockIdx.x, tid = threadIdx.x;
    const int wid = tid >> 5, lane = tid & 31;
    const float4* dr = (const float4*)(dots + (size_t)row * NTOK);
    const float4* ar = (const float4*)(Am   + (size_t)row * NTOK);
    const int dj = row >> 2, dl = row & 3;

    float mxr = -3.4e38f, mxm = -3.4e38f;
    #pragma unroll
    for (int j = tid; j < NTOK / 4; j += 256) {
        float4 d = dr[j], a = ar[j], v;
        v.x = (a.x > 0.0f) ? d.x : -9e15f;
        v.y = (a.y > 0.0f) ? d.y : -9e15f;
        v.z = (a.z > 0.0f) ? d.z : -9e15f;
        v.w = (a.w > 0.0f) ? d.w : -9e15f;
        if (j == dj) ((float*)&v)[dl] = 1.0f;
        rawv[j] = d; mskv[j] = v;
        mxr = fmaxf(fmaxf(fmaxf(mxr, d.x), d.y), fmaxf(d.z, d.w));
        mxm = fmaxf(fmaxf(fmaxf(mxm, v.x), v.y), fmaxf(v.z, v.w));
    }
    mxm = blk_max(mxm, wred, wid, lane);
    mxr = blk_max(mxr, wred, wid, lane);

    float sm = 0.0f, sr = 0.0f;
    #pragma unroll
    for (int j = tid; j < NTOK / 4; j += 256) {
        float4 v = mskv[j], d = rawv[j];
        v.x = __expf(v.x - mxm); v.y = __expf(v.y - mxm);
        v.z = __expf(v.z - mxm); v.w = __expf(v.w - mxm);
        d.x = __expf(d.x - mxr); d.y = __expf(d.y - mxr);
        d.z = __expf(d.z - mxr); d.w = __expf(d.w - mxr);
        mskv[j] = v; rawv[j] = d;
        sm += (v.x + v.y) + (v.z + v.w);
        sr += (d.x + d.y) + (d.z + d.w);
    }
    sm = blk_sum(sm, wred, wid, lane);
    sr = blk_sum(sr, wred, wid, lane);
    float invm = 1.0f / sm, invr = 1.0f / sr;

    float4* o1 = (float4*)(attn     + (size_t)row * NTOK);
    float4* o2 = (float4*)(attn_out + (size_t)row * NTOK);
    float4* o3 = (float4*)(ds_out   + (size_t)row * NTOK);
    #pragma unroll
    for (int j = tid; j < NTOK / 4; j += 256) {
        float4 v = mskv[j], d = rawv[j];
        float4 vo = make_float4(v.x * invm, v.y * invm, v.z * invm, v.w * invm);
        o1[j] = vo; o2[j] = vo;
        o3[j] = make_float4(d.x * invr, d.y * invr, d.z * invr, d.w * invr);
    }
}

// -------------------- host orchestration --------------------
extern "C" void kernel_launch(void* const* d_in, const int* in_sizes, int n_in,
                              void* d_out, int out_size)
{
    const float* embed = (const float*)d_in[0];
    const float* Am    = (const float*)d_in[1];
    const float* g1    = (const float*)d_in[2];
    const float* b1    = (const float*)d_in[3];
    const float* Wqkv  = (const float*)d_in[4];
    const float* Wout  = (const float*)d_in[5];
    const float* bout  = (const float*)d_in[6];
    const float* g2    = (const float*)d_in[7];
    const float* b2    = (const float*)d_in[8];
    const float* W1    = (const float*)d_in[9];
    const float* bb1   = (const float*)d_in[10];
    const float* W2    = (const float*)d_in[11];
    const float* bb2   = (const float*)d_in[12];
    const float* gf    = (const float*)d_in[13];
    const float* bf    = (const float*)d_in[14];

    float *xg, *xng, *qkvg, *dotsg, *attng, *avg, *vTg, *wTg;
    cudaGetSymbolAddress((void**)&xg,    g_x);
    cudaGetSymbolAddress((void**)&xng,   g_xn);
    cudaGetSymbolAddress((void**)&qkvg,  g_qkv);
    cudaGetSymbolAddress((void**)&dotsg, g_dots);
    cudaGetSymbolAddress((void**)&attng, g_attn);
    cudaGetSymbolAddress((void**)&avg,   g_av);
    cudaGetSymbolAddress((void**)&vTg,   g_vT);
    cudaGetSymbolAddress((void**)&wTg,   g_wT);

    cudaFuncSetAttribute(gemm_tc_k, cudaFuncAttributeMaxDynamicSharedMemorySize, GEMM_TC_SMEM);

    float* out_x    = (float*)d_out;
    float* out_attn = out_x + (size_t)ROWS * DIM64;
    float* out_ds   = out_attn + (size_t)NTOK * NTOK;

    dim3 blk(16, 16);
    dim3 tblk(32, 8);

    for (int l = 0; l < 2; l++) {
        const float* src = l ? xg : embed;
        // xn = LN(x)
        ln_k<<<ROWS / 8, 256>>>(src, g1 + l * 64, b1 + l * 64, xng, ROWS);
        // wT = Wqkv[l]^T   [64,768] -> [768,64]
        transpose_k<<<dim3(768 / 32, 64 / 32), tblk>>>(Wqkv + (size_t)l * 64 * 768, 768, wTg, 64);
        // qkv = xn @ Wqkv[l]  (NT with wT):  [8192,64] x [768,64]^T
        gemm_tc_k<<<dim3(768 / 128, ROWS / 128, 1), 256, GEMM_TC_SMEM>>>(
            xng, 64, 0, wTg, 64, 0, qkvg, 768, 0, 64, 1.0f);
        // dots = 0.125 * q0 @ k0^T  [4096,256] x [4096,256]^T (batch 0 only)
        gemm_tc_k<<<dim3(NTOK / 128, NTOK / 128, 1), 256, GEMM_TC_SMEM>>>(
            qkvg, 768, 0, qkvg + 256, 768, 0, dotsg, NTOK, 0, 256, 0.125f);
        // softmax
        if (l == 1)
            dual_softmax_k<<<NTOK, 256>>>(dotsg, Am, attng, out_attn, out_ds);
        else
            attn_softmax_k<<<NTOK, 256>>>(dotsg, Am, attng);
        // vT[z] = V[z]^T  ([4096,256] strided in qkv -> [256,4096])
        for (int z = 0; z < BATCH; z++)
            transpose_k<<<dim3(INNERD / 32, NTOK / 32), tblk>>>(
                qkvg + (size_t)z * NTOK * 768 + 512, 768,
                vTg + (size_t)z * INNERD * NTOK, NTOK);
        // av[z] = attn @ V[z]  (NT with vT): [4096,4096] x [256,4096]^T
        gemm_tc_k<<<dim3(INNERD / 128, NTOK / 128, BATCH), 256, GEMM_TC_SMEM>>>(
            attng, NTOK, 0,
            vTg, NTOK, (size_t)INNERD * NTOK,
            avg, INNERD, (size_t)NTOK * INNERD,
            NTOK, 1.0f);
        // x = xn + (av @ Wout[l] + bout[l])
        gemm_k<<<dim3(1, ROWS / 64), blk>>>(
            avg, INNERD, Wout + (size_t)l * INNERD * 64, 64, xg, 64, INNERD,
            bout + l * 64, xng, 0);
        // xm = LN(x)
        ln_k<<<ROWS / 8, 256>>>(xg, g2 + l * 64, b2 + l * 64, xng, ROWS);
        // h = gelu(xm @ W1 + bb1)
        gemm_k<<<dim3(1, ROWS / 64), blk>>>(
            xng, 64, W1 + (size_t)l * 64 * 64, 64, qkvg, 64, 64,
            bb1 + l * 64, nullptr, 1);
        // x = xm + (h @ W2 + bb2)
        gemm_k<<<dim3(1, ROWS / 64), blk>>>(
            qkvg, 64, W2 + (size_t)l * 64 * 64, 64, xg, 64, 64,
            bb2 + l * 64, xng, 0);
    }
    // final LN -> output
    ln_k<<<ROWS / 8, 256>>>(xg, gf, bf, out_x, ROWS);
}

// round 7
// speedup vs baseline: 3.9889x; 1.0363x over previous
#include <cuda_runtime.h>
#include <math.h>
#include <stdint.h>

#define NTOK   4096
#define BATCH  2
#define DIM64  64
#define INNERD 256
#define ROWS   (BATCH * NTOK)   // 8192

// -------------------- device scratch --------------------
__device__ float g_xn  [ROWS * DIM64];
__device__ float g_x   [ROWS * DIM64];
__device__ float g_qkv [ROWS * INNERD * 3];
__device__ float g_dots[(size_t)NTOK * NTOK];
__device__ float g_attn[(size_t)NTOK * NTOK];
__device__ float g_av  [ROWS * INNERD];           // used as [token][z*256+dh] = [4096][512]
__device__ float g_vT  [BATCH * INNERD * NTOK];   // [z*256+dh][token] = [512][4096]
__device__ float g_wT  [768 * 64];

// -------------------- helpers --------------------
__device__ __forceinline__ void mma_tf32(float c[4], const float a[4], const float b[2]) {
    asm volatile(
        "mma.sync.aligned.m16n8k8.row.col.f32.tf32.tf32.f32 "
        "{%0,%1,%2,%3}, {%4,%5,%6,%7}, {%8,%9}, {%0,%1,%2,%3};"
        : "+f"(c[0]), "+f"(c[1]), "+f"(c[2]), "+f"(c[3])
        : "r"(__float_as_uint(a[0])), "r"(__float_as_uint(a[1])),
          "r"(__float_as_uint(a[2])), "r"(__float_as_uint(a[3])),
          "r"(__float_as_uint(b[0])), "r"(__float_as_uint(b[1])));
}

__device__ __forceinline__ void cp16(uint32_t dst, const void* src) {
    asm volatile("cp.async.cg.shared.global [%0], [%1], 16;" :: "r"(dst), "l"(src));
}

// ==================== TF32 tensor-core NT GEMM, cp.async + frag pipelined ====================
// C[z][M,N] = alpha * A[z](M,K) * B[z](N,K)^T ; M,N mult of 128, K mult of 32.
// 256 threads, 8 warps (4M x 2N), warp tile 32x64, BK=32, 2-stage cp.async,
// fragment double-buffer across the four k8 sub-steps.
#define SPITCH 36
#define ASTG   (128 * SPITCH)
#define AS(p, m, k) sm[(p) * ASTG + (m) * SPITCH + (k)]
#define BS(p, n, k) sm[(2 + (p)) * ASTG + (n) * SPITCH + (k)]
#define GEMM_TC_SMEM (4 * ASTG * (int)sizeof(float))   // 73728 bytes

__global__ void __launch_bounds__(256)
gemm_tc_k(const float* __restrict__ A, int lda, size_t sAz,
          const float* __restrict__ B, int ldb, size_t sBz,
          float* __restrict__ C, int ldc, size_t sCz,
          int K, float alpha)
{
    extern __shared__ float sm[];
    const uint32_t smb = (uint32_t)__cvta_generic_to_shared(sm);
    const int tid  = threadIdx.x;
    const int wid  = tid >> 5, lane = tid & 31;
    const int wm   = wid & 3,  wn   = wid >> 2;
    const int gid  = lane >> 2, tig = lane & 3;
    const int m0   = blockIdx.y * 128, n0 = blockIdx.x * 128;

    A += (size_t)blockIdx.z * sAz;
    B += (size_t)blockIdx.z * sBz;
    C += (size_t)blockIdx.z * sCz;

    int lrow[4], lkq[4];
    #pragma unroll
    for (int i = 0; i < 4; i++) {
        int c = tid + i * 256;
        lrow[i] = c >> 3;
        lkq[i]  = (c & 7) << 2;
    }

    // cp.async one full stage (A-tile + B-tile) for k-tile kt into buffer s
#define ISSUE(s, kt)                                                                   \
    {                                                                                  \
        const int _k0 = (kt) << 5;                                                     \
        _Pragma("unroll")                                                              \
        for (int i = 0; i < 4; i++) {                                                  \
            cp16(smb + (uint32_t)(((s) * ASTG + lrow[i] * SPITCH + lkq[i]) * 4),       \
                 A + (size_t)(m0 + lrow[i]) * lda + _k0 + lkq[i]);                     \
            cp16(smb + (uint32_t)(((2 + (s)) * ASTG + lrow[i] * SPITCH + lkq[i]) * 4), \
                 B + (size_t)(n0 + lrow[i]) * ldb + _k0 + lkq[i]);                     \
        }                                                                              \
        asm volatile("cp.async.commit_group;");                                       \
    }

    float acc[2][8][4];
    #pragma unroll
    for (int mt = 0; mt < 2; mt++)
        #pragma unroll
        for (int nt = 0; nt < 8; nt++)
            #pragma unroll
            for (int q = 0; q < 4; q++) acc[mt][nt][q] = 0.0f;

    float fa[2][2][4];
    float fb[2][8][2];

#define FRAG_LOAD(buf, p, ks)                                            \
    {                                                                    \
        const int _kb = (ks) << 3;                                       \
        _Pragma("unroll")                                                \
        for (int mt = 0; mt < 2; mt++) {                                 \
            const int mr = wm * 32 + mt * 16 + gid;                      \
            fa[buf][mt][0] = AS(p, mr,     _kb + tig);                   \
            fa[buf][mt][1] = AS(p, mr + 8, _kb + tig);                   \
            fa[buf][mt][2] = AS(p, mr,     _kb + tig + 4);               \
            fa[buf][mt][3] = AS(p, mr + 8, _kb + tig + 4);               \
        }                                                                \
        _Pragma("unroll")                                                \
        for (int nt = 0; nt < 8; nt++) {                                 \
            const int nr = wn * 64 + nt * 8 + gid;                       \
            fb[buf][nt][0] = BS(p, nr, _kb + tig);                       \
            fb[buf][nt][1] = BS(p, nr, _kb + tig + 4);                   \
        }                                                                \
    }

#define MMA_STEP(buf)                                                    \
    {                                                                    \
        _Pragma("unroll")                                                \
        for (int nt = 0; nt < 8; nt++) {                                 \
            mma_tf32(acc[0][nt], fa[buf][0], fb[buf][nt]);               \
            mma_tf32(acc[1][nt], fa[buf][1], fb[buf][nt]);               \
        }                                                                \
    }

    const int KT = K >> 5;

    ISSUE(0, 0);
    if (KT > 1) {
        ISSUE(1, 1);
        asm volatile("cp.async.wait_group 1;");
    } else {
        asm volatile("cp.async.wait_group 0;");
    }
    __syncthreads();

    int buf = 0;
    FRAG_LOAD(0, 0, 0);

    for (int kt = 0; kt < KT; kt++) {
        const int p = kt & 1;
        #pragma unroll
        for (int ks = 0; ks < 4; ks++) {
            if (ks < 3) {
                FRAG_LOAD(buf ^ 1, p, ks + 1);
                MMA_STEP(buf);
                buf ^= 1;
            } else {
                if (kt + 1 < KT) {
                    __syncthreads();   // everyone's frags for stage p are in regs
                    if (kt + 2 < KT) {
                        ISSUE(p, kt + 2);
                        asm volatile("cp.async.wait_group 1;");
                    } else {
                        asm volatile("cp.async.wait_group 0;");
                    }
                    __syncthreads();   // stage p^1 now visible to all
                    FRAG_LOAD(buf ^ 1, p ^ 1, 0);
                }
                MMA_STEP(buf);
                buf ^= 1;
            }
        }
    }

    // epilogue
    #pragma unroll
    for (int mt = 0; mt < 2; mt++) {
        const int row = m0 + wm * 32 + mt * 16 + gid;
        #pragma unroll
        for (int nt = 0; nt < 8; nt++) {
            const int col = n0 + wn * 64 + nt * 8 + tig * 2;
            float2 v0 = make_float2(acc[mt][nt][0] * alpha, acc[mt][nt][1] * alpha);
            float2 v1 = make_float2(acc[mt][nt][2] * alpha, acc[mt][nt][3] * alpha);
            *(float2*)(C + (size_t)row * ldc + col)       = v0;
            *(float2*)(C + (size_t)(row + 8) * ldc + col) = v1;
        }
    }
#undef ISSUE
#undef FRAG_LOAD
#undef MMA_STEP
}

// -------------------- 32x32 transpose --------------------
__global__ void transpose_k(const float* __restrict__ src, int lds,
                            float* __restrict__ dst, int ldd)
{
    __shared__ float t[32][33];
    int c0 = blockIdx.x * 32, r0 = blockIdx.y * 32;
    int tx = threadIdx.x, ty = threadIdx.y;
    #pragma unroll
    for (int j = 0; j < 32; j += 8)
        t[ty + j][tx] = src[(size_t)(r0 + ty + j) * lds + c0 + tx];
    __syncthreads();
    #pragma unroll
    for (int j = 0; j < 32; j += 8)
        dst[(size_t)(c0 + ty + j) * ldd + r0 + tx] = t[tx][ty + j];
}

// -------------------- LayerNorm (dim 64) --------------------
__global__ void ln_k(const float* __restrict__ x, const float* __restrict__ g,
                     const float* __restrict__ b, float* __restrict__ y, int rows)
{
    int w    = blockIdx.x * 8 + (threadIdx.x >> 5);
    int lane = threadIdx.x & 31;
    if (w >= rows) return;
    const float* xr = x + (size_t)w * 64;
    float v0 = xr[lane], v1 = xr[lane + 32];
    float s = v0 + v1;
    #pragma unroll
    for (int o = 16; o > 0; o >>= 1) s += __shfl_xor_sync(0xffffffffu, s, o);
    float m  = s * (1.0f / 64.0f);
    float d0 = v0 - m, d1 = v1 - m;
    float q  = d0 * d0 + d1 * d1;
    #pragma unroll
    for (int o = 16; o > 0; o >>= 1) q += __shfl_xor_sync(0xffffffffu, q, o);
    float inv = rsqrtf(q * (1.0f / 64.0f) + 1e-5f);
    float* yr = y + (size_t)w * 64;
    yr[lane]      = d0 * inv * g[lane]      + b[lane];
    yr[lane + 32] = d1 * inv * g[lane + 32] + b[lane + 32];
}

// -------------------- small fp32 GEMM (N=64 projections, fused epilogue) ----------------
__global__ void __launch_bounds__(256)
gemm_k(const float* __restrict__ A, int lda,
       const float* __restrict__ B, int ldb,
       float* __restrict__ C, int ldc,
       int K,
       const float* __restrict__ bias,
       const float* __restrict__ resid, int ldr,
       int do_gelu)
{
    __shared__ float As[16][68];
    __shared__ float Bs[16][68];
    int tx = threadIdx.x, ty = threadIdx.y;
    int t  = ty * 16 + tx;
    int m0 = blockIdx.y * 64, n0 = blockIdx.x * 64;

    float acc[4][4] = {};
    int ar  = t / 4;
    int ac4 = (t % 4) * 4;
    int br  = t / 16;
    int bc4 = (t % 16) * 4;

    for (int k0 = 0; k0 < K; k0 += 16) {
        const float* Ap = A + (size_t)(m0 + ar) * lda + k0 + ac4;
        #pragma unroll
        for (int q = 0; q < 4; q++) As[ac4 + q][ar] = Ap[q];
        const float* Bp = B + (size_t)(k0 + br) * ldb + n0 + bc4;
        #pragma unroll
        for (int q = 0; q < 4; q++) Bs[br][bc4 + q] = Bp[q];
        __syncthreads();
        #pragma unroll
        for (int kk = 0; kk < 16; kk++) {
            float a[4], b[4];
            #pragma unroll
            for (int i = 0; i < 4; i++) a[i] = As[kk][ty * 4 + i];
            #pragma unroll
            for (int j = 0; j < 4; j++) b[j] = Bs[kk][tx * 4 + j];
            #pragma unroll
            for (int i = 0; i < 4; i++)
                #pragma unroll
                for (int j = 0; j < 4; j++)
                    acc[i][j] = fmaf(a[i], b[j], acc[i][j]);
        }
        __syncthreads();
    }

    #pragma unroll
    for (int i = 0; i < 4; i++) {
        int row = m0 + ty * 4 + i;
        #pragma unroll
        for (int j = 0; j < 4; j++) {
            int col = n0 + tx * 4 + j;
            float v = acc[i][j];
            if (bias)    v += bias[col];
            if (do_gelu) v = 0.5f * v * (1.0f + erff(v * 0.70710678118654752f));
            if (resid)   v += resid[(size_t)row * ldr + col];
            C[(size_t)row * ldc + col] = v;
        }
    }
}

// -------------------- block reductions --------------------
__device__ __forceinline__ float blk_max(float v, float* wred, int wid, int lane) {
    #pragma unroll
    for (int o = 16; o > 0; o >>= 1) v = fmaxf(v, __shfl_xor_sync(0xffffffffu, v, o));
    if (lane == 0) wred[wid] = v;
    __syncthreads();
    float r = wred[0];
    #pragma unroll
    for (int i = 1; i < 8; i++) r = fmaxf(r, wred[i]);
    __syncthreads();
    return r;
}
__device__ __forceinline__ float blk_sum(float v, float* wred, int wid, int lane) {
    #pragma unroll
    for (int o = 16; o > 0; o >>= 1) v += __shfl_xor_sync(0xffffffffu, v, o);
    if (lane == 0) wred[wid] = v;
    __syncthreads();
    float r = 0.0f;
    #pragma unroll
    for (int i = 0; i < 8; i++) r += wred[i];
    __syncthreads();
    return r;
}

// -------------------- masked softmax, register-resident --------------------
__global__ void attn_softmax_k(const float* __restrict__ dots, const float* __restrict__ Am,
                               float* __restrict__ attn)
{
    __shared__ float wred[8];
    const int row = blockIdx.x, tid = threadIdx.x;
    const int wid = tid >> 5, lane = tid & 31;
    const float4* dr = (const float4*)(dots + (size_t)row * NTOK);
    const float4* ar = (const float4*)(Am   + (size_t)row * NTOK);
    const int dj = row >> 2, dl = row & 3;

    float4 r[4];
    float mx = -3.4e38f;
    #pragma unroll
    for (int i = 0; i < 4; i++) {
        int j = tid + i * 256;
        float4 d = dr[j], a = ar[j], v;
        v.x = (a.x > 0.0f) ? d.x : -9e15f;
        v.y = (a.y > 0.0f) ? d.y : -9e15f;
        v.z = (a.z > 0.0f) ? d.z : -9e15f;
        v.w = (a.w > 0.0f) ? d.w : -9e15f;
        if (j == dj) ((float*)&v)[dl] = 1.0f;
        r[i] = v;
        mx = fmaxf(fmaxf(fmaxf(mx, v.x), v.y), fmaxf(v.z, v.w));
    }
    mx = blk_max(mx, wred, wid, lane);

    float sum = 0.0f;
    #pragma unroll
    for (int i = 0; i < 4; i++) {
        r[i].x = __expf(r[i].x - mx); r[i].y = __expf(r[i].y - mx);
        r[i].z = __expf(r[i].z - mx); r[i].w = __expf(r[i].w - mx);
        sum += (r[i].x + r[i].y) + (r[i].z + r[i].w);
    }
    sum = blk_sum(sum, wred, wid, lane);
    float inv = 1.0f / sum;

    float4* o1 = (float4*)(attn + (size_t)row * NTOK);
    #pragma unroll
    for (int i = 0; i < 4; i++) {
        int j = tid + i * 256;
        o1[j] = make_float4(r[i].x * inv, r[i].y * inv, r[i].z * inv, r[i].w * inv);
    }
}

// ----- last layer: masked softmax (attn + attn_out) AND plain softmax (ds_out) -----
__global__ void dual_softmax_k(const float* __restrict__ dots, const float* __restrict__ Am,
                               float* __restrict__ attn, float* __restrict__ attn_out,
                               float* __restrict__ ds_out)
{
    __shared__ float wred[8];
    const int row = blockIdx.x, tid = threadIdx.x;
    const int wid = tid >> 5, lane = tid & 31;
    const float4* dr = (const float4*)(dots + (size_t)row * NTOK);
    const float4* ar = (const float4*)(Am   + (size_t)row * NTOK);
    const int dj = row >> 2, dl = row & 3;

    float4 rv[4], mv[4];
    float mxr = -3.4e38f, mxm = -3.4e38f;
    #pragma unroll
    for (int i = 0; i < 4; i++) {
        int j = tid + i * 256;
        float4 d = dr[j], a = ar[j], v;
        v.x = (a.x > 0.0f) ? d.x : -9e15f;
        v.y = (a.y > 0.0f) ? d.y : -9e15f;
        v.z = (a.z > 0.0f) ? d.z : -9e15f;
        v.w = (a.w > 0.0f) ? d.w : -9e15f;
        if (j == dj) ((float*)&v)[dl] = 1.0f;
        rv[i] = d; mv[i] = v;
        mxr = fmaxf(fmaxf(fmaxf(mxr, d.x), d.y), fmaxf(d.z, d.w));
        mxm = fmaxf(fmaxf(fmaxf(mxm, v.x), v.y), fmaxf(v.z, v.w));
    }
    mxm = blk_max(mxm, wred, wid, lane);
    mxr = blk_max(mxr, wred, wid, lane);

    float sm = 0.0f, sr = 0.0f;
    #pragma unroll
    for (int i = 0; i < 4; i++) {
        mv[i].x = __expf(mv[i].x - mxm); mv[i].y = __expf(mv[i].y - mxm);
        mv[i].z = __expf(mv[i].z - mxm); mv[i].w = __expf(mv[i].w - mxm);
        rv[i].x = __expf(rv[i].x - mxr); rv[i].y = __expf(rv[i].y - mxr);
        rv[i].z = __expf(rv[i].z - mxr); rv[i].w = __expf(rv[i].w - mxr);
        sm += (mv[i].x + mv[i].y) + (mv[i].z + mv[i].w);
        sr += (rv[i].x + rv[i].y) + (rv[i].z + rv[i].w);
    }
    sm = blk_sum(sm, wred, wid, lane);
    sr = blk_sum(sr, wred, wid, lane);
    float invm = 1.0f / sm, invr = 1.0f / sr;

    float4* o1 = (float4*)(attn     + (size_t)row * NTOK);
    float4* o2 = (float4*)(attn_out + (size_t)row * NTOK);
    float4* o3 = (float4*)(ds_out   + (size_t)row * NTOK);
    #pragma unroll
    for (int i = 0; i < 4; i++) {
        int j = tid + i * 256;
        float4 vo = make_float4(mv[i].x * invm, mv[i].y * invm, mv[i].z * invm, mv[i].w * invm);
        o1[j] = vo; o2[j] = vo;
        o3[j] = make_float4(rv[i].x * invr, rv[i].y * invr, rv[i].z * invr, rv[i].w * invr);
    }
}

// -------------------- host orchestration --------------------
extern "C" void kernel_launch(void* const* d_in, const int* in_sizes, int n_in,
                              void* d_out, int out_size)
{
    const float* embed = (const float*)d_in[0];
    const float* Am    = (const float*)d_in[1];
    const float* g1    = (const float*)d_in[2];
    const float* b1    = (const float*)d_in[3];
    const float* Wqkv  = (const float*)d_in[4];
    const float* Wout  = (const float*)d_in[5];
    const float* bout  = (const float*)d_in[6];
    const float* g2    = (const float*)d_in[7];
    const float* b2    = (const float*)d_in[8];
    const float* W1    = (const float*)d_in[9];
    const float* bb1   = (const float*)d_in[10];
    const float* W2    = (const float*)d_in[11];
    const float* bb2   = (const float*)d_in[12];
    const float* gf    = (const float*)d_in[13];
    const float* bf    = (const float*)d_in[14];

    float *xg, *xng, *qkvg, *dotsg, *attng, *avg, *vTg, *wTg;
    cudaGetSymbolAddress((void**)&xg,    g_x);
    cudaGetSymbolAddress((void**)&xng,   g_xn);
    cudaGetSymbolAddress((void**)&qkvg,  g_qkv);
    cudaGetSymbolAddress((void**)&dotsg, g_dots);
    cudaGetSymbolAddress((void**)&attng, g_attn);
    cudaGetSymbolAddress((void**)&avg,   g_av);
    cudaGetSymbolAddress((void**)&vTg,   g_vT);
    cudaGetSymbolAddress((void**)&wTg,   g_wT);

    cudaFuncSetAttribute(gemm_tc_k, cudaFuncAttributeMaxDynamicSharedMemorySize, GEMM_TC_SMEM);

    float* out_x    = (float*)d_out;
    float* out_attn = out_x + (size_t)ROWS * DIM64;
    float* out_ds   = out_attn + (size_t)NTOK * NTOK;

    dim3 blk(16, 16);
    dim3 tblk(32, 8);

    for (int l = 0; l < 2; l++) {
        const float* src = l ? xg : embed;
        // xn = LN(x)
        ln_k<<<ROWS / 8, 256>>>(src, g1 + l * 64, b1 + l * 64, xng, ROWS);
        // wT = Wqkv[l]^T
        transpose_k<<<dim3(768 / 32, 64 / 32), tblk>>>(Wqkv + (size_t)l * 64 * 768, 768, wTg, 64);
        // qkv = xn @ Wqkv[l] (NT):  [8192,64] x [768,64]^T
        gemm_tc_k<<<dim3(768 / 128, ROWS / 128, 1), 256, GEMM_TC_SMEM>>>(
            xng, 64, 0, wTg, 64, 0, qkvg, 768, 0, 64, 1.0f);
        // dots = 0.125 * q0 @ k0^T  (batch 0 only)
        gemm_tc_k<<<dim3(NTOK / 128, NTOK / 128, 1), 256, GEMM_TC_SMEM>>>(
            qkvg, 768, 0, qkvg + 256, 768, 0, dotsg, NTOK, 0, 256, 0.125f);
        // softmax
        if (l == 1)
            dual_softmax_k<<<NTOK, 256>>>(dotsg, Am, attng, out_attn, out_ds);
        else
            attn_softmax_k<<<NTOK, 256>>>(dotsg, Am, attng);
        // vT[z*256+dh][token] = V (both batches -> [512,4096] contiguous)
        for (int z = 0; z < BATCH; z++)
            transpose_k<<<dim3(INNERD / 32, NTOK / 32), tblk>>>(
                qkvg + (size_t)z * NTOK * 768 + 512, 768,
                vTg + (size_t)z * INNERD * NTOK, NTOK);
        // av[token][z*256+dh] = attn @ [vT]^T : single GEMM [4096,512]
        gemm_tc_k<<<dim3(512 / 128, NTOK / 128, 1), 256, GEMM_TC_SMEM>>>(
            attng, NTOK, 0, vTg, NTOK, 0, avg, 512, 0, NTOK, 1.0f);
        // x[z] = xn[z] + (av[:, z-half] @ Wout[l] + bout[l])
        for (int z = 0; z < BATCH; z++)
            gemm_k<<<dim3(1, NTOK / 64), blk>>>(
                avg + z * INNERD, 512, Wout + (size_t)l * INNERD * 64, 64,
                xg + (size_t)z * NTOK * 64, 64, INNERD,
                bout + l * 64, xng + (size_t)z * NTOK * 64, 64, 0);
        // xm = LN(x)
        ln_k<<<ROWS / 8, 256>>>(xg, g2 + l * 64, b2 + l * 64, xng, ROWS);
        // h = gelu(xm @ W1 + bb1)
        gemm_k<<<dim3(1, ROWS / 64), blk>>>(
            xng, 64, W1 + (size_t)l * 64 * 64, 64, qkvg, 64, 64,
            bb1 + l * 64, nullptr, 64, 1);
        // x = xm + (h @ W2 + bb2)
        gemm_k<<<dim3(1, ROWS / 64), blk>>>(
            qkvg, 64, W2 + (size_t)l * 64 * 64, 64, xg, 64, 64,
            bb2 + l * 64, xng, 64, 0);
    }
    // final LN -> output
    ln_k<<<ROWS / 8, 256>>>(xg, gf, bf, out_x, ROWS);
}

// round 9
// speedup vs baseline: 4.2909x; 1.0757x over previous
#include <cuda_runtime.h>
#include <math.h>
#include <stdint.h>

#define NTOK   4096
#define BATCH  2
#define DIM64  64
#define INNERD 256
#define ROWS   (BATCH * NTOK)   // 8192

// -------------------- device scratch --------------------
__device__ float g_xn  [ROWS * DIM64];
__device__ float g_x   [ROWS * DIM64];
__device__ float g_qkv [ROWS * INNERD * 3];
__device__ float g_dots[(size_t)NTOK * NTOK];     // also reused as split-K partials after softmax
__device__ float g_attn[(size_t)NTOK * NTOK];
__device__ float g_av  [ROWS * INNERD];           // [token][z*256+dh] = [4096][512]
__device__ float g_vT  [BATCH * INNERD * NTOK];   // [z*256+dh][token] = [512][4096]
__device__ float g_wT  [768 * 64];

// -------------------- helpers --------------------
__device__ __forceinline__ void mma_tf32(float c[4], const float a[4], const float b[2]) {
    asm volatile(
        "mma.sync.aligned.m16n8k8.row.col.f32.tf32.tf32.f32 "
        "{%0,%1,%2,%3}, {%4,%5,%6,%7}, {%8,%9}, {%0,%1,%2,%3};"
        : "+f"(c[0]), "+f"(c[1]), "+f"(c[2]), "+f"(c[3])
        : "r"(__float_as_uint(a[0])), "r"(__float_as_uint(a[1])),
          "r"(__float_as_uint(a[2])), "r"(__float_as_uint(a[3])),
          "r"(__float_as_uint(b[0])), "r"(__float_as_uint(b[1])));
}

__device__ __forceinline__ void cp16(uint32_t dst, const void* src) {
    asm volatile("cp.async.cg.shared.global [%0], [%1], 16;" :: "r"(dst), "l"(src));
}

// ==================== TF32 tensor-core NT GEMM, 2 CTAs/SM ====================
// C[z][M,N] = alpha * A[z](M,K) * B[z](N,K)^T ; M,N mult of 128, K mult of 32.
// z strides are ELEMENT offsets (use as K-offset for split-K).
// 256 threads, 8 warps (4M x 2N), warp tile 32x64, BK=32, 2-stage cp.async.
#define SPITCH 36
#define ASTG   (128 * SPITCH)
#define AS(p, m, k) sm[(p) * ASTG + (m) * SPITCH + (k)]
#define BS(p, n, k) sm[(2 + (p)) * ASTG + (n) * SPITCH + (k)]
#define GEMM_TC_SMEM (4 * ASTG * (int)sizeof(float))   // 73728 bytes

__global__ void __launch_bounds__(256, 2)
gemm_tc_k(const float* __restrict__ A, int lda, size_t sAz,
          const float* __restrict__ B, int ldb, size_t sBz,
          float* __restrict__ C, int ldc, size_t sCz,
          int K, float alpha)
{
    extern __shared__ float sm[];
    const uint32_t smb = (uint32_t)__cvta_generic_to_shared(sm);
    const int tid  = threadIdx.x;
    const int wid  = tid >> 5, lane = tid & 31;
    const int wm   = wid & 3,  wn   = wid >> 2;
    const int gid  = lane >> 2, tig = lane & 3;
    const int m0   = blockIdx.y * 128, n0 = blockIdx.x * 128;

    A += (size_t)blockIdx.z * sAz;
    B += (size_t)blockIdx.z * sBz;
    C += (size_t)blockIdx.z * sCz;

    int lrow[4], lkq[4];
    #pragma unroll
    for (int i = 0; i < 4; i++) {
        int c = tid + i * 256;
        lrow[i] = c >> 3;
        lkq[i]  = (c & 7) << 2;
    }

#define ISSUE(s, kt)                                                                   \
    {                                                                                  \
        const int _k0 = (kt) << 5;                                                     \
        _Pragma("unroll")                                                              \
        for (int i = 0; i < 4; i++) {                                                  \
            cp16(smb + (uint32_t)(((s) * ASTG + lrow[i] * SPITCH + lkq[i]) * 4),       \
                 A + (size_t)(m0 + lrow[i]) * lda + _k0 + lkq[i]);                     \
            cp16(smb + (uint32_t)(((2 + (s)) * ASTG + lrow[i] * SPITCH + lkq[i]) * 4), \
                 B + (size_t)(n0 + lrow[i]) * ldb + _k0 + lkq[i]);                     \
        }                                                                              \
        asm volatile("cp.async.commit_group;");                                       \
    }

    float acc[2][8][4];
    #pragma unroll
    for (int mt = 0; mt < 2; mt++)
        #pragma unroll
        for (int nt = 0; nt < 8; nt++)
            #pragma unroll
            for (int q = 0; q < 4; q++) acc[mt][nt][q] = 0.0f;

    const int KT = K >> 5;
    ISSUE(0, 0);

    for (int kt = 0; kt < KT; kt++) {
        const int p = kt & 1;
        if (kt + 1 < KT) {
            ISSUE(p ^ 1, kt + 1);
            asm volatile("cp.async.wait_group 1;");
        } else {
            asm volatile("cp.async.wait_group 0;");
        }
        __syncthreads();   // stage p visible to all warps

        #pragma unroll
        for (int ks = 0; ks < 4; ks++) {
            const int kb = ks << 3;
            float fa[2][4];
            float fb[8][2];
            #pragma unroll
            for (int mt = 0; mt < 2; mt++) {
                const int mr = wm * 32 + mt * 16 + gid;
                fa[mt][0] = AS(p, mr,     kb + tig);
                fa[mt][1] = AS(p, mr + 8, kb + tig);
                fa[mt][2] = AS(p, mr,     kb + tig + 4);
                fa[mt][3] = AS(p, mr + 8, kb + tig + 4);
            }
            #pragma unroll
            for (int nt = 0; nt < 8; nt++) {
                const int nr = wn * 64 + nt * 8 + gid;
                fb[nt][0] = BS(p, nr, kb + tig);
                fb[nt][1] = BS(p, nr, kb + tig + 4);
            }
            #pragma unroll
            for (int nt = 0; nt < 8; nt++) {
                mma_tf32(acc[0][nt], fa[0], fb[nt]);
                mma_tf32(acc[1][nt], fa[1], fb[nt]);
            }
        }
        __syncthreads();   // all reads of stage p done before it is overwritten
    }

    // epilogue
    #pragma unroll
    for (int mt = 0; mt < 2; mt++) {
        const int row = m0 + wm * 32 + mt * 16 + gid;
        #pragma unroll
        for (int nt = 0; nt < 8; nt++) {
            const int col = n0 + wn * 64 + nt * 8 + tig * 2;
            float2 v0 = make_float2(acc[mt][nt][0] * alpha, acc[mt][nt][1] * alpha);
            float2 v1 = make_float2(acc[mt][nt][2] * alpha, acc[mt][nt][3] * alpha);
            *(float2*)(C + (size_t)row * ldc + col)       = v0;
            *(float2*)(C + (size_t)(row + 8) * ldc + col) = v1;
        }
    }
#undef ISSUE
}

// -------------------- split-K reduction: o = a + b (float4) --------------------
__global__ void add2_k(const float* __restrict__ a, const float* __restrict__ b,
                       float* __restrict__ o, int n4)
{
    int i = blockIdx.x * blockDim.x + threadIdx.x;
    if (i < n4) {
        float4 x = ((const float4*)a)[i], y = ((const float4*)b)[i];
        ((float4*)o)[i] = make_float4(x.x + y.x, x.y + y.y, x.z + y.z, x.w + y.w);
    }
}

// -------------------- 32x32 transpose --------------------
__global__ void transpose_k(const float* __restrict__ src, int lds,
                            float* __restrict__ dst, int ldd)
{
    __shared__ float t[32][33];
    int c0 = blockIdx.x * 32, r0 = blockIdx.y * 32;
    int tx = threadIdx.x, ty = threadIdx.y;
    #pragma unroll
    for (int j = 0; j < 32; j += 8)
        t[ty + j][tx] = src[(size_t)(r0 + ty + j) * lds + c0 + tx];
    __syncthreads();
    #pragma unroll
    for (int j = 0; j < 32; j += 8)
        dst[(size_t)(c0 + ty + j) * ldd + r0 + tx] = t[tx][ty + j];
}

// -------------------- LayerNorm (dim 64) --------------------
__global__ void ln_k(const float* __restrict__ x, const float* __restrict__ g,
                     const float* __restrict__ b, float* __restrict__ y, int rows)
{
    int w    = blockIdx.x * 8 + (threadIdx.x >> 5);
    int lane = threadIdx.x & 31;
    if (w >= rows) return;
    const float* xr = x + (size_t)w * 64;
    float v0 = xr[lane], v1 = xr[lane + 32];
    float s = v0 + v1;
    #pragma unroll
    for (int o = 16; o > 0; o >>= 1) s += __shfl_xor_sync(0xffffffffu, s, o);
    float m  = s * (1.0f / 64.0f);
    float d0 = v0 - m, d1 = v1 - m;
    float q  = d0 * d0 + d1 * d1;
    #pragma unroll
    for (int o = 16; o > 0; o >>= 1) q += __shfl_xor_sync(0xffffffffu, q, o);
    float inv = rsqrtf(q * (1.0f / 64.0f) + 1e-5f);
    float* yr = y + (size_t)w * 64;
    yr[lane]      = d0 * inv * g[lane]      + b[lane];
    yr[lane + 32] = d1 * inv * g[lane + 32] + b[lane + 32];
}

// -------------------- small fp32 GEMM (N=64 projections, fused epilogue) ----------------
__global__ void __launch_bounds__(256)
gemm_k(const float* __restrict__ A, int lda,
       const float* __restrict__ B, int ldb,
       float* __restrict__ C, int ldc,
       int K,
       const float* __restrict__ bias,
       const float* __restrict__ resid, int ldr,
       int do_gelu)
{
    __shared__ float As[16][68];
    __shared__ float Bs[16][68];
    int tx = threadIdx.x, ty = threadIdx.y;
    int t  = ty * 16 + tx;
    int m0 = blockIdx.y * 64, n0 = blockIdx.x * 64;

    float acc[4][4] = {};
    int ar  = t / 4;
    int ac4 = (t % 4) * 4;
    int br  = t / 16;
    int bc4 = (t % 16) * 4;

    for (int k0 = 0; k0 < K; k0 += 16) {
        const float* Ap = A + (size_t)(m0 + ar) * lda + k0 + ac4;
        #pragma unroll
        for (int q = 0; q < 4; q++) As[ac4 + q][ar] = Ap[q];
        const float* Bp = B + (size_t)(k0 + br) * ldb + n0 + bc4;
        #pragma unroll
        for (int q = 0; q < 4; q++) Bs[br][bc4 + q] = Bp[q];
        __syncthreads();
        #pragma unroll
        for (int kk = 0; kk < 16; kk++) {
            float a[4], b[4];
            #pragma unroll
            for (int i = 0; i < 4; i++) a[i] = As[kk][ty * 4 + i];
            #pragma unroll
            for (int j = 0; j < 4; j++) b[j] = Bs[kk][tx * 4 + j];
            #pragma unroll
            for (int i = 0; i < 4; i++)
                #pragma unroll
                for (int j = 0; j < 4; j++)
                    acc[i][j] = fmaf(a[i], b[j], acc[i][j]);
        }
        __syncthreads();
    }

    #pragma unroll
    for (int i = 0; i < 4; i++) {
        int row = m0 + ty * 4 + i;
        #pragma unroll
        for (int j = 0; j < 4; j++) {
            int col = n0 + tx * 4 + j;
            float v = acc[i][j];
            if (bias)    v += bias[col];
            if (do_gelu) v = 0.5f * v * (1.0f + erff(v * 0.70710678118654752f));
            if (resid)   v += resid[(size_t)row * ldr + col];
            C[(size_t)row * ldc + col] = v;
        }
    }
}

// -------------------- block reductions --------------------
__device__ __forceinline__ float blk_max(float v, float* wred, int wid, int lane) {
    #pragma unroll
    for (int o = 16; o > 0; o >>= 1) v = fmaxf(v, __shfl_xor_sync(0xffffffffu, v, o));
    if (lane == 0) wred[wid] = v;
    __syncthreads();
    float r = wred[0];
    #pragma unroll
    for (int i = 1; i < 8; i++) r = fmaxf(r, wred[i]);
    __syncthreads();
    return r;
}
__device__ __forceinline__ float blk_sum(float v, float* wred, int wid, int lane) {
    #pragma unroll
    for (int o = 16; o > 0; o >>= 1) v += __shfl_xor_sync(0xffffffffu, v, o);
    if (lane == 0) wred[wid] = v;
    __syncthreads();
    float r = 0.0f;
    #pragma unroll
    for (int i = 0; i < 8; i++) r += wred[i];
    __syncthreads();
    return r;
}

// -------------------- masked softmax, register-resident --------------------
__global__ void attn_softmax_k(const float* __restrict__ dots, const float* __restrict__ Am,
                               float* __restrict__ attn)
{
    __shared__ float wred[8];
    const int row = blockIdx.x, tid = threadIdx.x;
    const int wid = tid >> 5, lane = tid & 31;
    const float4* dr = (const float4*)(dots + (size_t)row * NTOK);
    const float4* ar = (const float4*)(Am   + (size_t)row * NTOK);
    const int dj = row >> 2, dl = row & 3;

    float4 r[4];
    float mx = -3.4e38f;
    #pragma unroll
    for (int i = 0; i < 4; i++) {
        int j = tid + i * 256;
        float4 d = dr[j], a = ar[j], v;
        v.x = (a.x > 0.0f) ? d.x : -9e15f;
        v.y = (a.y > 0.0f) ? d.y : -9e15f;
        v.z = (a.z > 0.0f) ? d.z : -9e15f;
        v.w = (a.w > 0.0f) ? d.w : -9e15f;
        if (j == dj) ((float*)&v)[dl] = 1.0f;
        r[i] = v;
        mx = fmaxf(fmaxf(fmaxf(mx, v.x), v.y), fmaxf(v.z, v.w));
    }
    mx = blk_max(mx, wred, wid, lane);

    float sum = 0.0f;
    #pragma unroll
    for (int i = 0; i < 4; i++) {
        r[i].x = __expf(r[i].x - mx); r[i].y = __expf(r[i].y - mx);
        r[i].z = __expf(r[i].z - mx); r[i].w = __expf(r[i].w - mx);
        sum += (r[i].x + r[i].y) + (r[i].z + r[i].w);
    }
    sum = blk_sum(sum, wred, wid, lane);
    float inv = 1.0f / sum;

    float4* o1 = (float4*)(attn + (size_t)row * NTOK);
    #pragma unroll
    for (int i = 0; i < 4; i++) {
        int j = tid + i * 256;
        o1[j] = make_float4(r[i].x * inv, r[i].y * inv, r[i].z * inv, r[i].w * inv);
    }
}

// ----- last layer: masked softmax (attn + attn_out) AND plain softmax (ds_out) -----
__global__ void dual_softmax_k(const float* __restrict__ dots, const float* __restrict__ Am,
                               float* __restrict__ attn, float* __restrict__ attn_out,
                               float* __restrict__ ds_out)
{
    __shared__ float wred[8];
    const int row = blockIdx.x, tid = threadIdx.x;
    const int wid = tid >> 5, lane = tid & 31;
    const float4* dr = (const float4*)(dots + (size_t)row * NTOK);
    const float4* ar = (const float4*)(Am   + (size_t)row * NTOK);
    const int dj = row >> 2, dl = row & 3;

    float4 rv[4], mv[4];
    float mxr = -3.4e38f, mxm = -3.4e38f;
    #pragma unroll
    for (int i = 0; i < 4; i++) {
        int j = tid + i * 256;
        float4 d = dr[j], a = ar[j], v;
        v.x = (a.x > 0.0f) ? d.x : -9e15f;
        v.y = (a.y > 0.0f) ? d.y : -9e15f;
        v.z = (a.z > 0.0f) ? d.z : -9e15f;
        v.w = (a.w > 0.0f) ? d.w : -9e15f;
        if (j == dj) ((float*)&v)[dl] = 1.0f;
        rv[i] = d; mv[i] = v;
        mxr = fmaxf(fmaxf(fmaxf(mxr, d.x), d.y), fmaxf(d.z, d.w));
        mxm = fmaxf(fmaxf(fmaxf(mxm, v.x), v.y), fmaxf(v.z, v.w));
    }
    mxm = blk_max(mxm, wred, wid, lane);
    mxr = blk_max(mxr, wred, wid, lane);

    float sm = 0.0f, sr = 0.0f;
    #pragma unroll
    for (int i = 0; i < 4; i++) {
        mv[i].x = __expf(mv[i].x - mxm); mv[i].y = __expf(mv[i].y - mxm);
        mv[i].z = __expf(mv[i].z - mxm); mv[i].w = __expf(mv[i].w - mxm);
        rv[i].x = __expf(rv[i].x - mxr); rv[i].y = __expf(rv[i].y - mxr);
        rv[i].z = __expf(rv[i].z - mxr); rv[i].w = __expf(rv[i].w - mxr);
        sm += (mv[i].x + mv[i].y) + (mv[i].z + mv[i].w);
        sr += (rv[i].x + rv[i].y) + (rv[i].z + rv[i].w);
    }
    sm = blk_sum(sm, wred, wid, lane);
    sr = blk_sum(sr, wred, wid, lane);
    float invm = 1.0f / sm, invr = 1.0f / sr;

    float4* o1 = (float4*)(attn     + (size_t)row * NTOK);
    float4* o2 = (float4*)(attn_out + (size_t)row * NTOK);
    float4* o3 = (float4*)(ds_out   + (size_t)row * NTOK);
    #pragma unroll
    for (int i = 0; i < 4; i++) {
        int j = tid + i * 256;
        float4 vo = make_float4(mv[i].x * invm, mv[i].y * invm, mv[i].z * invm, mv[i].w * invm);
        o1[j] = vo; o2[j] = vo;
        o3[j] = make_float4(rv[i].x * invr, rv[i].y * invr, rv[i].z * invr, rv[i].w * invr);
    }
}

// -------------------- host orchestration --------------------
extern "C" void kernel_launch(void* const* d_in, const int* in_sizes, int n_in,
                              void* d_out, int out_size)
{
    const float* embed = (const float*)d_in[0];
    const float* Am    = (const float*)d_in[1];
    const float* g1    = (const float*)d_in[2];
    const float* b1    = (const float*)d_in[3];
    const float* Wqkv  = (const float*)d_in[4];
    const float* Wout  = (const float*)d_in[5];
    const float* bout  = (const float*)d_in[6];
    const float* g2    = (const float*)d_in[7];
    const float* b2    = (const float*)d_in[8];
    const float* W1    = (const float*)d_in[9];
    const float* bb1   = (const float*)d_in[10];
    const float* W2    = (const float*)d_in[11];
    const float* bb2   = (const float*)d_in[12];
    const float* gf    = (const float*)d_in[13];
    const float* bf    = (const float*)d_in[14];

    float *xg, *xng, *qkvg, *dotsg, *attng, *avg, *vTg, *wTg;
    cudaGetSymbolAddress((void**)&xg,    g_x);
    cudaGetSymbolAddress((void**)&xng,   g_xn);
    cudaGetSymbolAddress((void**)&qkvg,  g_qkv);
    cudaGetSymbolAddress((void**)&dotsg, g_dots);
    cudaGetSymbolAddress((void**)&attng, g_attn);
    cudaGetSymbolAddress((void**)&avg,   g_av);
    cudaGetSymbolAddress((void**)&vTg,   g_vT);
    cudaGetSymbolAddress((void**)&wTg,   g_wT);

    cudaFuncSetAttribute(gemm_tc_k, cudaFuncAttributeMaxDynamicSharedMemorySize, GEMM_TC_SMEM);

    float* out_x    = (float*)d_out;
    float* out_attn = out_x + (size_t)ROWS * DIM64;
    float* out_ds   = out_attn + (size_t)NTOK * NTOK;

    dim3 blk(16, 16);
    dim3 tblk(32, 8);
    const size_t avHalf = (size_t)NTOK * 512;   // split-K partial stride (in g_dots)

    for (int l = 0; l < 2; l++) {
        const float* src = l ? xg : embed;
        // xn = LN(x)
        ln_k<<<ROWS / 8, 256>>>(src, g1 + l * 64, b1 + l * 64, xng, ROWS);
        // wT = Wqkv[l]^T
        transpose_k<<<dim3(768 / 32, 64 / 32), tblk>>>(Wqkv + (size_t)l * 64 * 768, 768, wTg, 64);
        // qkv = xn @ Wqkv[l] (NT): [8192,64] x [768,64]^T
        gemm_tc_k<<<dim3(768 / 128, ROWS / 128, 1), 256, GEMM_TC_SMEM>>>(
            xng, 64, 0, wTg, 64, 0, qkvg, 768, 0, 64, 1.0f);
        // dots = 0.125 * q0 @ k0^T (batch 0 only)
        gemm_tc_k<<<dim3(NTOK / 128, NTOK / 128, 1), 256, GEMM_TC_SMEM>>>(
            qkvg, 768, 0, qkvg + 256, 768, 0, dotsg, NTOK, 0, 256, 0.125f);
        // softmax
        if (l == 1)
            dual_softmax_k<<<NTOK, 256>>>(dotsg, Am, attng, out_attn, out_ds);
        else
            attn_softmax_k<<<NTOK, 256>>>(dotsg, Am, attng);
        // vT (both batches -> [512,4096] contiguous)
        for (int z = 0; z < BATCH; z++)
            transpose_k<<<dim3(INNERD / 32, NTOK / 32), tblk>>>(
                qkvg + (size_t)z * NTOK * 768 + 512, 768,
                vTg + (size_t)z * INNERD * NTOK, NTOK);
        // av = attn @ vT^T, split-K x2 (dots scratch is free after softmax):
        // z strides shift the K window by 2048; partials at dotsg + z*avHalf
        gemm_tc_k<<<dim3(512 / 128, NTOK / 128, 2), 256, GEMM_TC_SMEM>>>(
            attng, NTOK, 2048, vTg, NTOK, 2048, dotsg, 512, avHalf, 2048, 1.0f);
        add2_k<<<(int)(avHalf / 4 + 255) / 256, 256>>>(dotsg, dotsg + avHalf, avg, (int)(avHalf / 4));
        // x[z] = xn[z] + (av[:, z-half] @ Wout[l] + bout[l])
        for (int z = 0; z < BATCH; z++)
            gemm_k<<<dim3(1, NTOK / 64), blk>>>(
                avg + z * INNERD, 512, Wout + (size_t)l * INNERD * 64, 64,
                xg + (size_t)z * NTOK * 64, 64, INNERD,
                bout + l * 64, xng + (size_t)z * NTOK * 64, 64, 0);
        // xm = LN(x)
        ln_k<<<ROWS / 8, 256>>>(xg, g2 + l * 64, b2 + l * 64, xng, ROWS);
        // h = gelu(xm @ W1 + bb1)
        gemm_k<<<dim3(1, ROWS / 64), blk>>>(
            xng, 64, W1 + (size_t)l * 64 * 64, 64, qkvg, 64, 64,
            bb1 + l * 64, nullptr, 64, 1);
        // x = xm + (h @ W2 + bb2)
        gemm_k<<<dim3(1, ROWS / 64), blk>>>(
            qkvg, 64, W2 + (size_t)l * 64 * 64, 64, xg, 64, 64,
            bb2 + l * 64, xng, 64, 0);
    }
    // final LN -> output
    ln_k<<<ROWS / 8, 256>>>(xg, gf, bf, out_x, ROWS);
}